// round 9
// baseline (speedup 1.0000x reference)
#include <cuda_runtime.h>

#define NB 8
#define NC 256
#define NP 4096
#define NPQ 4224

__device__ float g_pq[NB * NC * NPQ];
__device__ float g_pk[NB * NC * NPQ];
__device__ float g_pv[NB * NPQ * NC];
__device__ float g_go[NB * NC * NPQ];
__device__ float g_p [NB * NC * NPQ];
__device__ int   g_pr[NB * NP];
__device__ int   g_cidx[NB * NP];
__device__ int   g_cnt[NB * 2];

typedef unsigned long long ull;

__device__ __forceinline__ ull pack2(float lo, float hi) {
    ull r; asm("mov.b64 %0, {%1, %2};" : "=l"(r) : "f"(lo), "f"(hi)); return r;
}
__device__ __forceinline__ float2 unpack2(ull v) {
    float2 r; asm("mov.b64 {%0, %1}, %2;" : "=f"(r.x), "=f"(r.y) : "l"(v)); return r;
}
__device__ __forceinline__ ull fma2(ull a, ull b, ull c) {
    ull d; asm("fma.rn.f32x2 %0, %1, %2, %3;" : "=l"(d) : "l"(a), "l"(b), "l"(c)); return d;
}
__device__ __forceinline__ ull mul2(ull a, ull b) {
    ull d; asm("mul.rn.f32x2 %0, %1, %2;" : "=l"(d) : "l"(a), "l"(b)); return d;
}
__device__ __forceinline__ void cp16(void* dst, const void* src) {
    unsigned s = (unsigned)__cvta_generic_to_shared(dst);
    asm volatile("cp.async.cg.shared.global [%0], [%1], 16;" :: "r"(s), "l"(src));
}
__device__ __forceinline__ void cp4(void* dst, const void* src) {
    unsigned s = (unsigned)__cvta_generic_to_shared(dst);
    asm volatile("cp.async.ca.shared.global [%0], [%1], 4;" :: "r"(s), "l"(src));
}
#define CP_COMMIT asm volatile("cp.async.commit_group;" ::: "memory")
#define CP_WAIT(n) asm volatile("cp.async.wait_group %0;" :: "n"(n) : "memory")

// ============================ compaction ===================================
__global__ __launch_bounds__(256, 1) void compact_kernel(const float* __restrict__ mask)
{
    const int b = blockIdx.x;
    const int tid = threadIdx.x;
    const int lane = tid & 31, wid = tid >> 5;
    __shared__ int wsum[8];
    __shared__ int s_nf;

    bool f[16];
    int c = 0;
    const float* mb = mask + (size_t)b * NP;
    #pragma unroll
    for (int i = 0; i < 16; i++) { f[i] = mb[tid * 16 + i] > 0.5f; c += f[i]; }

    int v = c;
    #pragma unroll
    for (int off = 1; off < 32; off <<= 1) {
        int u = __shfl_up_sync(0xffffffffu, v, off);
        if (lane >= off) v += u;
    }
    if (lane == 31) wsum[wid] = v;
    __syncthreads();
    if (tid < 8) {
        int wv = wsum[tid];
        #pragma unroll
        for (int off = 1; off < 8; off <<= 1) {
            int u = __shfl_up_sync(0xffu, wv, off);
            if (tid >= off) wv += u;
        }
        wsum[tid] = wv;
        if (tid == 7) s_nf = wv;
    }
    __syncthreads();
    const int nf = s_nf;
    int excl = v - c + (wid ? wsum[wid - 1] : 0);
    int fo = excl;
    int bo = tid * 16 - excl;

    int* pr   = g_pr   + (size_t)b * NP;
    int* cidx = g_cidx + (size_t)b * NP;
    #pragma unroll
    for (int i = 0; i < 16; i++) {
        int n = tid * 16 + i;
        if (f[i]) { pr[n] = fo; cidx[n] = fo; fo++; }
        else      { pr[n] = bo; cidx[n] = nf; bo++; }
    }
    if (tid == 0) { g_cnt[b * 2] = nf; g_cnt[b * 2 + 1] = NP - nf; }
}

// ============================ QKV projection ===============================
__global__ __launch_bounds__(256, 2) void qkv_kernel(
    const float* __restrict__ x, const float* __restrict__ mask,
    const float* __restrict__ Wq, const float* __restrict__ bq,
    const float* __restrict__ Wk, const float* __restrict__ bk,
    const float* __restrict__ Wv, const float* __restrict__ bv)
{
    __shared__ float Ws[2][32][132];
    __shared__ float Xs[2][32][64];

    const int tid = threadIdx.x;
    const int tx = tid & 15;
    const int ty = tid >> 4;
    const int n0 = blockIdx.x * 64;
    const int m0 = blockIdx.y * 128;
    const int b  = blockIdx.z;

    ull acc[4][4];
    #pragma unroll
    for (int mp = 0; mp < 4; mp++)
        #pragma unroll
        for (int jj = 0; jj < 4; jj++) acc[mp][jj] = 0ull;

    auto issue = [&](int ci, int buf) {
        const int kc = ci * 32;
        #pragma unroll
        for (int it = 0; it < 16; it++) {
            int idx = tid + it * 256;
            int m = idx >> 5, kk = idx & 31;
            int mg = m0 + m;
            const float* Wp = (mg < 256) ? Wq : ((mg < 512) ? Wk : Wv);
            cp4(&Ws[buf][kk][m], &Wp[(mg & 255) * 256 + kc + kk]);
        }
        #pragma unroll
        for (int it = 0; it < 2; it++) {
            int idx = tid + it * 256;
            int k = idx >> 4, j4 = idx & 15;
            cp16(&Xs[buf][k][j4 * 4], &x[(size_t)(b * NC + kc + k) * NP + n0 + j4 * 4]);
        }
        CP_COMMIT;
    };

    issue(0, 0);
    for (int ci = 0; ci < 8; ci++) {
        int nxt = (ci + 1 < 8) ? ci + 1 : 7;
        issue(nxt, (ci + 1) & 1);
        CP_WAIT(1);
        __syncthreads();
        const int buf = ci & 1;
        #pragma unroll 8
        for (int k = 0; k < 32; k++) {
            ulonglong2 w01 = *reinterpret_cast<const ulonglong2*>(&Ws[buf][k][ty * 8]);
            ulonglong2 w23 = *reinterpret_cast<const ulonglong2*>(&Ws[buf][k][ty * 8 + 4]);
            float4 xv = *reinterpret_cast<const float4*>(&Xs[buf][k][tx * 4]);
            ull wp[4] = { w01.x, w01.y, w23.x, w23.y };
            ull xd[4] = { pack2(xv.x, xv.x), pack2(xv.y, xv.y),
                          pack2(xv.z, xv.z), pack2(xv.w, xv.w) };
            #pragma unroll
            for (int mp = 0; mp < 4; mp++)
                #pragma unroll
                for (int jj = 0; jj < 4; jj++)
                    acc[mp][jj] = fma2(wp[mp], xd[jj], acc[mp][jj]);
        }
        __syncthreads();
    }
    CP_WAIT(0);

    const int sel = m0 >> 8;
    const int nbase = n0 + tx * 4;
    float mk[4]; int pr[4];
    #pragma unroll
    for (int jj = 0; jj < 4; jj++) {
        mk[jj] = mask[(size_t)b * NP + nbase + jj];
        pr[jj] = g_pr[(size_t)b * NP + nbase + jj];
    }

    #pragma unroll
    for (int mp = 0; mp < 4; mp++) {
        float2 u[4];
        #pragma unroll
        for (int jj = 0; jj < 4; jj++) u[jj] = unpack2(acc[mp][jj]);
        #pragma unroll
        for (int h = 0; h < 2; h++) {
            const int o = (m0 & 255) + ty * 8 + mp * 2 + h;
            float val[4];
            val[0] = h ? u[0].y : u[0].x;
            val[1] = h ? u[1].y : u[1].x;
            val[2] = h ? u[2].y : u[2].x;
            val[3] = h ? u[3].y : u[3].x;
            if (sel == 0) {
                const float bb = bq[o];
                float* dst = g_pq + (size_t)(b * NC + o) * NPQ;
                #pragma unroll
                for (int jj = 0; jj < 4; jj++)
                    if (mk[jj] > 0.5f) dst[pr[jj]] = val[jj] + bb;
            } else if (sel == 1) {
                const float bb = bk[o];
                float* dst = g_pk + (size_t)(b * NC + o) * NPQ;
                #pragma unroll
                for (int jj = 0; jj < 4; jj++)
                    if (mk[jj] < 0.5f) dst[pr[jj]] = val[jj] + bb;
            } else {
                const float bb = bv[o];
                #pragma unroll
                for (int jj = 0; jj < 4; jj++)
                    if (mk[jj] < 0.5f)
                        g_pv[((size_t)b * NPQ + pr[jj]) * NC + o] = val[jj] + bb;
            }
        }
    }
}

// ============================ pad ==========================================
__global__ __launch_bounds__(256, 1) void pad_kernel(
    const float* __restrict__ bq, const float* __restrict__ bk,
    const float* __restrict__ bv)
{
    const int b = blockIdx.x;
    const int sec = blockIdx.y;
    const int tid = threadIdx.x;
    const int nf = g_cnt[b * 2];
    const int nb = g_cnt[b * 2 + 1];

    if (sec == 0) {
        const int NQ = ((nf + 64) >> 6) << 6;
        const int npad = NQ - nf;
        for (int idx = tid; idx < npad * NC; idx += 256) {
            int c = idx / npad, p = nf + idx % npad;
            g_pq[(size_t)(b * NC + c) * NPQ + p] = (p == nf) ? bq[c] : 0.f;
        }
    } else if (sec == 1) {
        const int NK = ((nb + 128) >> 7) << 7;
        const int npad = NK - nb;
        for (int idx = tid; idx < npad * NC; idx += 256) {
            int c = idx / npad, p = nb + idx % npad;
            g_pk[(size_t)(b * NC + c) * NPQ + p] = (p == nb) ? bk[c] : 0.f;
        }
    } else {
        const int NK = ((nb + 128) >> 7) << 7;
        for (int p = nb; p < NK; p++)
            g_pv[((size_t)b * NPQ + p) * NC + tid] = (p == nb) ? bv[tid] : 0.f;
    }
}

// ============================ flash attention ==============================
// 512 thr, tile 64q x 128k. S: jl=tid&15 -> j quad (jhalf*16+jl)*4,
// rowg=(tid>>4)&15 -> rows rowg*4..+3, jhalf=tid>>8. K in four 64c x 128j
// chunks (32KB). PV: c0=jl*4+jhalf*64, quads {c0, c0+128}; V in two
// 64j x 256c halves (64KB). Pool 4x32KB: K ping-pongs in two while V
// streams through the other two.
__global__ __launch_bounds__(512, 1) void attn_kernel()
{
    extern __shared__ float smf[];
    float* Qs   = smf;              // [256c][64i] 16384
    float* Pool = smf + 16384;      // 4 x 8192
    float* Ps   = smf + 49152;      // [64i][128j] 8192
    float* Red  = smf + 57344;      // 256

    const int tid   = threadIdx.x;
    const int jl    = tid & 15;
    const int rowg  = (tid >> 4) & 15;
    const int jhalf = tid >> 8;
    const int b  = blockIdx.y;
    const int i0 = blockIdx.x * 64;

    const int nf = g_cnt[b * 2];
    const int nb = g_cnt[b * 2 + 1];
    if (i0 >= nf + 1) return;
    const int nkt = (nb + 128) >> 7;
    const float wF = (float)nf;
    const int c0 = jl * 4 + jhalf * 64;

    auto PB = [&](int i) { return Pool + i * 8192; };

    auto loadK = [&](int ck, int j0, float* buf) {
        const float* src = g_pk + (size_t)(b * NC + ck * 64) * NPQ + j0;
        #pragma unroll
        for (int it = 0; it < 4; it++) {
            int idx = tid + it * 512;
            int c = idx >> 5, j4 = idx & 31;
            cp16(&buf[c * 128 + j4 * 4], &src[(size_t)c * NPQ + j4 * 4]);
        }
        CP_COMMIT;
    };
    auto loadV = [&](int vh, int j0, float* buf) {
        const float* src = g_pv + ((size_t)b * NPQ + j0 + vh * 64) * NC;
        #pragma unroll
        for (int it = 0; it < 8; it++) {
            int idx = tid + it * 512;
            int j = idx >> 6, c4 = idx & 63;
            cp16(&buf[j * 256 + c4 * 4], &src[(size_t)j * NC + c4 * 4]);
        }
        CP_COMMIT;
    };

    // prologue: Q + K chunk0 of tile 0 in one group
    #pragma unroll
    for (int it = 0; it < 8; it++) {
        int idx = tid + it * 512;
        int c = idx >> 4, i4 = idx & 15;
        cp16(&Qs[c * 64 + i4 * 4], &g_pq[(size_t)(b * NC + c) * NPQ + i0 + i4 * 4]);
    }
    loadK(0, 0, PB(0));

    float m_i[4], l_i[4];
    #pragma unroll
    for (int ii = 0; ii < 4; ii++) { m_i[ii] = -1e30f; l_i[ii] = 0.f; }
    ulonglong2 oa[2][4];
    #pragma unroll
    for (int q = 0; q < 2; q++)
        #pragma unroll
        for (int ii = 0; ii < 4; ii++) { oa[q][ii].x = 0ull; oa[q][ii].y = 0ull; }

    ull s2[2][4];

    auto sphase = [&](int p, const float* Kb) {
        const float* qb = Qs + (p * 64) * 64 + rowg * 4;
        const float* kb = Kb + (jhalf * 16 + jl) * 4;
        #pragma unroll 8
        for (int c = 0; c < 64; c++) {
            ulonglong2 q2 = *reinterpret_cast<const ulonglong2*>(qb + c * 64);
            float4 k4 = *reinterpret_cast<const float4*>(kb + c * 128);
            ull kd0 = pack2(k4.x, k4.x), kd1 = pack2(k4.y, k4.y);
            ull kd2 = pack2(k4.z, k4.z), kd3 = pack2(k4.w, k4.w);
            s2[0][0] = fma2(q2.x, kd0, s2[0][0]); s2[1][0] = fma2(q2.y, kd0, s2[1][0]);
            s2[0][1] = fma2(q2.x, kd1, s2[0][1]); s2[1][1] = fma2(q2.y, kd1, s2[1][1]);
            s2[0][2] = fma2(q2.x, kd2, s2[0][2]); s2[1][2] = fma2(q2.y, kd2, s2[1][2]);
            s2[0][3] = fma2(q2.x, kd3, s2[0][3]); s2[1][3] = fma2(q2.y, kd3, s2[1][3]);
        }
    };

    auto pvphase = [&](int jb, const float* Vb) {
        #pragma unroll 2
        for (int j4 = 0; j4 < 16; j4++) {
            float4 pr[4];
            #pragma unroll
            for (int ii = 0; ii < 4; ii++)
                pr[ii] = *reinterpret_cast<const float4*>(&Ps[(rowg * 4 + ii) * 128 + jb + j4 * 4]);
            #pragma unroll
            for (int dj = 0; dj < 4; dj++) {
                const float* vrow = Vb + (j4 * 4 + dj) * 256;
                ulonglong2 v0 = *reinterpret_cast<const ulonglong2*>(vrow + c0);
                ulonglong2 v1 = *reinterpret_cast<const ulonglong2*>(vrow + c0 + 128);
                #pragma unroll
                for (int ii = 0; ii < 4; ii++) {
                    float p = (dj == 0) ? pr[ii].x : (dj == 1) ? pr[ii].y
                            : (dj == 2) ? pr[ii].z : pr[ii].w;
                    ull pd = pack2(p, p);
                    oa[0][ii].x = fma2(v0.x, pd, oa[0][ii].x);
                    oa[0][ii].y = fma2(v0.y, pd, oa[0][ii].y);
                    oa[1][ii].x = fma2(v1.x, pd, oa[1][ii].x);
                    oa[1][ii].y = fma2(v1.y, pd, oa[1][ii].y);
                }
            }
        }
    };

    for (int jt = 0; jt < nkt; jt++) {
        const int j0 = jt << 7;
        const int kb = (jt & 1) ? 2 : 0;
        const int vb = 2 - kb;

        #pragma unroll
        for (int ip = 0; ip < 2; ip++)
            #pragma unroll
            for (int jj = 0; jj < 4; jj++) s2[ip][jj] = 0ull;

        CP_WAIT(0); __syncthreads();
        loadK(1, j0, PB(kb ^ 1));
        sphase(0, PB(kb));

        CP_WAIT(0); __syncthreads();
        loadK(2, j0, PB(kb));
        sphase(1, PB(kb ^ 1));

        CP_WAIT(0); __syncthreads();
        loadK(3, j0, PB(kb ^ 1));          // group A
        loadV(0, j0, PB(vb));              // group B -> PB(vb),PB(vb+1)
        sphase(2, PB(kb));

        CP_WAIT(1); __syncthreads();       // K3 done, V0 in flight
        sphase(3, PB(kb ^ 1));

        // ---- softmax over the 128-key tile ----
        {
            float sv[4][4];
            #pragma unroll
            for (int ip = 0; ip < 2; ip++)
                #pragma unroll
                for (int jj = 0; jj < 4; jj++) {
                    float2 u = unpack2(s2[ip][jj]);
                    sv[ip * 2 + 0][jj] = u.x;
                    sv[ip * 2 + 1][jj] = u.y;
                }
            const int jb2 = j0 + (jhalf * 16 + jl) * 4;
            float w[4];
            #pragma unroll
            for (int jj = 0; jj < 4; jj++) {
                int jg = jb2 + jj;
                w[jj] = (jg == nb) ? wF : 1.f;
                if (jg > nb) {
                    #pragma unroll
                    for (int ii = 0; ii < 4; ii++) sv[ii][jj] = -1e30f;
                }
            }
            float mloc[4];
            #pragma unroll
            for (int ii = 0; ii < 4; ii++) {
                float rm = fmaxf(fmaxf(sv[ii][0], sv[ii][1]), fmaxf(sv[ii][2], sv[ii][3]));
                #pragma unroll
                for (int off = 1; off < 16; off <<= 1)
                    rm = fmaxf(rm, __shfl_xor_sync(0xffffffffu, rm, off));
                mloc[ii] = rm;
            }
            if (jl == 0) {
                #pragma unroll
                for (int ii = 0; ii < 4; ii++)
                    Red[jhalf * 64 + rowg * 4 + ii] = mloc[ii];
            }
            __syncthreads();
            float alpha[4], rsum[4];
            #pragma unroll
            for (int ii = 0; ii < 4; ii++) {
                int row = rowg * 4 + ii;
                float mt = fmaxf(Red[row], Red[64 + row]);
                float mn = fmaxf(m_i[ii], mt);
                alpha[ii] = __expf(m_i[ii] - mn);
                m_i[ii] = mn;
                float p0 = __expf(sv[ii][0] - mn) * w[0];
                float p1 = __expf(sv[ii][1] - mn) * w[1];
                float p2 = __expf(sv[ii][2] - mn) * w[2];
                float p3 = __expf(sv[ii][3] - mn) * w[3];
                *reinterpret_cast<float4*>(&Ps[row * 128 + jhalf * 64 + jl * 4]) =
                    make_float4(p0, p1, p2, p3);
                float s = p0 + p1 + p2 + p3;
                #pragma unroll
                for (int off = 1; off < 16; off <<= 1)
                    s += __shfl_xor_sync(0xffffffffu, s, off);
                rsum[ii] = s;
            }
            if (jl == 0) {
                #pragma unroll
                for (int ii = 0; ii < 4; ii++)
                    Red[128 + jhalf * 64 + rowg * 4 + ii] = rsum[ii];
            }
            __syncthreads();
            #pragma unroll
            for (int ii = 0; ii < 4; ii++) {
                int row = rowg * 4 + ii;
                l_i[ii] = l_i[ii] * alpha[ii] + Red[128 + row] + Red[192 + row];
                ull ad = pack2(alpha[ii], alpha[ii]);
                oa[0][ii].x = mul2(oa[0][ii].x, ad);
                oa[0][ii].y = mul2(oa[0][ii].y, ad);
                oa[1][ii].x = mul2(oa[1][ii].x, ad);
                oa[1][ii].y = mul2(oa[1][ii].y, ad);
            }
        }

        CP_WAIT(0); __syncthreads();       // V0 ready; Ps visible
        loadV(1, j0, PB(kb));              // V1 -> PB(kb),PB(kb+1)
        pvphase(0, PB(vb));

        CP_WAIT(0); __syncthreads();
        {
            const int jn = (jt + 1 < nkt) ? (jt + 1) << 7 : j0;
            loadK(0, jn, PB(vb));          // next tile's K base == PB(vb)
        }
        pvphase(64, PB(kb));
    }
    CP_WAIT(0);

    float inv[4];
    #pragma unroll
    for (int ii = 0; ii < 4; ii++) inv[ii] = 1.f / l_i[ii];

    #pragma unroll
    for (int q = 0; q < 2; q++) {
        float of[4][4];
        #pragma unroll
        for (int ii = 0; ii < 4; ii++) {
            float2 u0 = unpack2(oa[q][ii].x);
            float2 u1 = unpack2(oa[q][ii].y);
            of[ii][0] = u0.x * inv[ii];
            of[ii][1] = u0.y * inv[ii];
            of[ii][2] = u1.x * inv[ii];
            of[ii][3] = u1.y * inv[ii];
        }
        #pragma unroll
        for (int d = 0; d < 4; d++) {
            int c = c0 + q * 128 + d;
            *reinterpret_cast<float4*>(&g_go[(size_t)(b * NC + c) * NPQ + i0 + rowg * 4]) =
                make_float4(of[0][d], of[1][d], of[2][d], of[3][d]);
        }
    }
}

// ============================ output projection ============================
__global__ __launch_bounds__(256, 2) void proj_kernel(
    const float* __restrict__ Wo, const float* __restrict__ bo)
{
    __shared__ float Ws[32][132];
    __shared__ float Xs[32][64];

    const int tid = threadIdx.x;
    const int tx = tid & 15;
    const int ty = tid >> 4;
    const int n0 = blockIdx.x * 64;
    const int m0 = blockIdx.y * 128;
    const int b  = blockIdx.z;

    const int nfq = g_cnt[b * 2] + 1;
    if (n0 >= nfq) return;

    ull acc[4][4];
    #pragma unroll
    for (int mp = 0; mp < 4; mp++)
        #pragma unroll
        for (int jj = 0; jj < 4; jj++) acc[mp][jj] = 0ull;

    for (int kc = 0; kc < NC; kc += 32) {
        #pragma unroll
        for (int it = 0; it < 16; it++) {
            int idx = tid + it * 256;
            int m = idx >> 5, kk = idx & 31;
            Ws[kk][m] = Wo[(m0 + m) * 256 + kc + kk];
        }
        #pragma unroll
        for (int it = 0; it < 2; it++) {
            int idx = tid + it * 256;
            int k = idx >> 4, j4 = idx & 15;
            *reinterpret_cast<float4*>(&Xs[k][j4 * 4]) =
                *reinterpret_cast<const float4*>(&g_go[(size_t)(b * NC + kc + k) * NPQ + n0 + j4 * 4]);
        }
        __syncthreads();
        #pragma unroll 8
        for (int k = 0; k < 32; k++) {
            ulonglong2 w01 = *reinterpret_cast<const ulonglong2*>(&Ws[k][ty * 8]);
            ulonglong2 w23 = *reinterpret_cast<const ulonglong2*>(&Ws[k][ty * 8 + 4]);
            float4 xv = *reinterpret_cast<const float4*>(&Xs[k][tx * 4]);
            ull wp[4] = { w01.x, w01.y, w23.x, w23.y };
            ull xd[4] = { pack2(xv.x, xv.x), pack2(xv.y, xv.y),
                          pack2(xv.z, xv.z), pack2(xv.w, xv.w) };
            #pragma unroll
            for (int mp = 0; mp < 4; mp++)
                #pragma unroll
                for (int jj = 0; jj < 4; jj++)
                    acc[mp][jj] = fma2(wp[mp], xd[jj], acc[mp][jj]);
        }
        __syncthreads();
    }

    #pragma unroll
    for (int mp = 0; mp < 4; mp++) {
        float2 u[4];
        #pragma unroll
        for (int jj = 0; jj < 4; jj++) u[jj] = unpack2(acc[mp][jj]);
        #pragma unroll
        for (int h = 0; h < 2; h++) {
            int o = m0 + ty * 8 + mp * 2 + h;
            float bb = bo[o];
            float4 r;
            r.x = (h ? u[0].y : u[0].x) + bb;
            r.y = (h ? u[1].y : u[1].x) + bb;
            r.z = (h ? u[2].y : u[2].x) + bb;
            r.w = (h ? u[3].y : u[3].x) + bb;
            *reinterpret_cast<float4*>(&g_p[(size_t)(b * NC + o) * NPQ + n0 + tx * 4]) = r;
        }
    }
}

// ============================ scatter ======================================
__global__ __launch_bounds__(256, 1) void scatter_kernel(
    const float* __restrict__ x, const float* __restrict__ gamma,
    float* __restrict__ out)
{
    const int b = blockIdx.y;
    const int n = blockIdx.x * 256 + threadIdx.x;
    const int ci = g_cidx[(size_t)b * NP + n];
    const float g0 = gamma[0];

    const float* px = x + (size_t)b * NC * NP + n;
    const float* pp = g_p + (size_t)b * NC * NPQ + ci;
    float* po = out + (size_t)b * NC * NP + n;

    #pragma unroll 4
    for (int c = 0; c < NC; c++) {
        po[(size_t)c * NP] = pp[(size_t)c * NPQ] + g0 * px[(size_t)c * NP];
    }
}

extern "C" void kernel_launch(void* const* d_in, const int* in_sizes, int n_in,
                              void* d_out, int out_size)
{
    const float* x     = (const float*)d_in[0];
    const float* mask  = (const float*)d_in[1];
    const float* Wq    = (const float*)d_in[2];
    const float* bq    = (const float*)d_in[3];
    const float* Wk    = (const float*)d_in[4];
    const float* bk    = (const float*)d_in[5];
    const float* Wv    = (const float*)d_in[6];
    const float* bv    = (const float*)d_in[7];
    const float* Wo    = (const float*)d_in[8];
    const float* bo    = (const float*)d_in[9];
    const float* gamma = (const float*)d_in[10];
    float* out = (float*)d_out;

    compact_kernel<<<NB, 256>>>(mask);
    qkv_kernel<<<dim3(64, 6, NB), 256>>>(x, mask, Wq, bq, Wk, bk, Wv, bv);
    pad_kernel<<<dim3(NB, 3), 256>>>(bq, bk, bv);

    const size_t smemB = (size_t)(16384 + 32768 + 8192 + 256) * sizeof(float);  // 230400 B
    cudaFuncSetAttribute(attn_kernel, cudaFuncAttributeMaxDynamicSharedMemorySize, (int)smemB);
    attn_kernel<<<dim3(65, NB), 512, smemB>>>();

    proj_kernel<<<dim3(65, 2, NB), 256>>>(Wo, bo);
    scatter_kernel<<<dim3(16, NB), 256>>>(x, gamma, out);
}

// round 10
// speedup vs baseline: 1.0009x; 1.0009x over previous
#include <cuda_runtime.h>

#define NB 8
#define NC 256
#define NP 4096
#define NPQ 4224

__device__ float g_pq[NB * NC * NPQ];
__device__ float g_pk[NB * NC * NPQ];
__device__ float g_pv[NB * NPQ * NC];
__device__ float g_go[NB * NC * NPQ];
__device__ float g_p [NB * NC * NPQ];
__device__ int   g_pr[NB * NP];
__device__ int   g_cidx[NB * NP];
__device__ int   g_cnt[NB * 2];

typedef unsigned long long ull;

__device__ __forceinline__ ull pack2(float lo, float hi) {
    ull r; asm("mov.b64 %0, {%1, %2};" : "=l"(r) : "f"(lo), "f"(hi)); return r;
}
__device__ __forceinline__ float2 unpack2(ull v) {
    float2 r; asm("mov.b64 {%0, %1}, %2;" : "=f"(r.x), "=f"(r.y) : "l"(v)); return r;
}
__device__ __forceinline__ ull fma2(ull a, ull b, ull c) {
    ull d; asm("fma.rn.f32x2 %0, %1, %2, %3;" : "=l"(d) : "l"(a), "l"(b), "l"(c)); return d;
}
__device__ __forceinline__ ull mul2(ull a, ull b) {
    ull d; asm("mul.rn.f32x2 %0, %1, %2;" : "=l"(d) : "l"(a), "l"(b)); return d;
}
__device__ __forceinline__ void cp16(void* dst, const void* src) {
    unsigned s = (unsigned)__cvta_generic_to_shared(dst);
    asm volatile("cp.async.cg.shared.global [%0], [%1], 16;" :: "r"(s), "l"(src));
}
__device__ __forceinline__ void cp4(void* dst, const void* src) {
    unsigned s = (unsigned)__cvta_generic_to_shared(dst);
    asm volatile("cp.async.ca.shared.global [%0], [%1], 4;" :: "r"(s), "l"(src));
}
#define CP_COMMIT asm volatile("cp.async.commit_group;" ::: "memory")
#define CP_WAIT(n) asm volatile("cp.async.wait_group %0;" :: "n"(n) : "memory")

// ============================ compaction ===================================
__global__ __launch_bounds__(256, 1) void compact_kernel(const float* __restrict__ mask)
{
    const int b = blockIdx.x;
    const int tid = threadIdx.x;
    const int lane = tid & 31, wid = tid >> 5;
    __shared__ int wsum[8];
    __shared__ int s_nf;

    bool f[16];
    int c = 0;
    const float* mb = mask + (size_t)b * NP;
    #pragma unroll
    for (int i = 0; i < 16; i++) { f[i] = mb[tid * 16 + i] > 0.5f; c += f[i]; }

    int v = c;
    #pragma unroll
    for (int off = 1; off < 32; off <<= 1) {
        int u = __shfl_up_sync(0xffffffffu, v, off);
        if (lane >= off) v += u;
    }
    if (lane == 31) wsum[wid] = v;
    __syncthreads();
    if (tid < 8) {
        int wv = wsum[tid];
        #pragma unroll
        for (int off = 1; off < 8; off <<= 1) {
            int u = __shfl_up_sync(0xffu, wv, off);
            if (tid >= off) wv += u;
        }
        wsum[tid] = wv;
        if (tid == 7) s_nf = wv;
    }
    __syncthreads();
    const int nf = s_nf;
    int excl = v - c + (wid ? wsum[wid - 1] : 0);
    int fo = excl;
    int bo = tid * 16 - excl;

    int* pr   = g_pr   + (size_t)b * NP;
    int* cidx = g_cidx + (size_t)b * NP;
    #pragma unroll
    for (int i = 0; i < 16; i++) {
        int n = tid * 16 + i;
        if (f[i]) { pr[n] = fo; cidx[n] = fo; fo++; }
        else      { pr[n] = bo; cidx[n] = nf; bo++; }
    }
    if (tid == 0) { g_cnt[b * 2] = nf; g_cnt[b * 2 + 1] = NP - nf; }
}

// ============================ QKV projection ===============================
__global__ __launch_bounds__(256, 2) void qkv_kernel(
    const float* __restrict__ x, const float* __restrict__ mask,
    const float* __restrict__ Wq, const float* __restrict__ bq,
    const float* __restrict__ Wk, const float* __restrict__ bk,
    const float* __restrict__ Wv, const float* __restrict__ bv)
{
    __shared__ float Ws[2][32][132];
    __shared__ float Xs[2][32][64];

    const int tid = threadIdx.x;
    const int tx = tid & 15;
    const int ty = tid >> 4;
    const int n0 = blockIdx.x * 64;
    const int m0 = blockIdx.y * 128;
    const int b  = blockIdx.z;

    ull acc[4][4];
    #pragma unroll
    for (int mp = 0; mp < 4; mp++)
        #pragma unroll
        for (int jj = 0; jj < 4; jj++) acc[mp][jj] = 0ull;

    auto issue = [&](int ci, int buf) {
        const int kc = ci * 32;
        #pragma unroll
        for (int it = 0; it < 16; it++) {
            int idx = tid + it * 256;
            int m = idx >> 5, kk = idx & 31;
            int mg = m0 + m;
            const float* Wp = (mg < 256) ? Wq : ((mg < 512) ? Wk : Wv);
            cp4(&Ws[buf][kk][m], &Wp[(mg & 255) * 256 + kc + kk]);
        }
        #pragma unroll
        for (int it = 0; it < 2; it++) {
            int idx = tid + it * 256;
            int k = idx >> 4, j4 = idx & 15;
            cp16(&Xs[buf][k][j4 * 4], &x[(size_t)(b * NC + kc + k) * NP + n0 + j4 * 4]);
        }
        CP_COMMIT;
    };

    issue(0, 0);
    for (int ci = 0; ci < 8; ci++) {
        int nxt = (ci + 1 < 8) ? ci + 1 : 7;
        issue(nxt, (ci + 1) & 1);
        CP_WAIT(1);
        __syncthreads();
        const int buf = ci & 1;
        #pragma unroll 8
        for (int k = 0; k < 32; k++) {
            ulonglong2 w01 = *reinterpret_cast<const ulonglong2*>(&Ws[buf][k][ty * 8]);
            ulonglong2 w23 = *reinterpret_cast<const ulonglong2*>(&Ws[buf][k][ty * 8 + 4]);
            float4 xv = *reinterpret_cast<const float4*>(&Xs[buf][k][tx * 4]);
            ull wp[4] = { w01.x, w01.y, w23.x, w23.y };
            ull xd[4] = { pack2(xv.x, xv.x), pack2(xv.y, xv.y),
                          pack2(xv.z, xv.z), pack2(xv.w, xv.w) };
            #pragma unroll
            for (int mp = 0; mp < 4; mp++)
                #pragma unroll
                for (int jj = 0; jj < 4; jj++)
                    acc[mp][jj] = fma2(wp[mp], xd[jj], acc[mp][jj]);
        }
        __syncthreads();
    }
    CP_WAIT(0);

    const int sel = m0 >> 8;
    const int nbase = n0 + tx * 4;
    float mk[4]; int pr[4];
    #pragma unroll
    for (int jj = 0; jj < 4; jj++) {
        mk[jj] = mask[(size_t)b * NP + nbase + jj];
        pr[jj] = g_pr[(size_t)b * NP + nbase + jj];
    }

    #pragma unroll
    for (int mp = 0; mp < 4; mp++) {
        float2 u[4];
        #pragma unroll
        for (int jj = 0; jj < 4; jj++) u[jj] = unpack2(acc[mp][jj]);
        #pragma unroll
        for (int h = 0; h < 2; h++) {
            const int o = (m0 & 255) + ty * 8 + mp * 2 + h;
            float val[4];
            val[0] = h ? u[0].y : u[0].x;
            val[1] = h ? u[1].y : u[1].x;
            val[2] = h ? u[2].y : u[2].x;
            val[3] = h ? u[3].y : u[3].x;
            if (sel == 0) {
                const float bb = bq[o];
                float* dst = g_pq + (size_t)(b * NC + o) * NPQ;
                #pragma unroll
                for (int jj = 0; jj < 4; jj++)
                    if (mk[jj] > 0.5f) dst[pr[jj]] = val[jj] + bb;
            } else if (sel == 1) {
                const float bb = bk[o];
                float* dst = g_pk + (size_t)(b * NC + o) * NPQ;
                #pragma unroll
                for (int jj = 0; jj < 4; jj++)
                    if (mk[jj] < 0.5f) dst[pr[jj]] = val[jj] + bb;
            } else {
                const float bb = bv[o];
                #pragma unroll
                for (int jj = 0; jj < 4; jj++)
                    if (mk[jj] < 0.5f)
                        g_pv[((size_t)b * NPQ + pr[jj]) * NC + o] = val[jj] + bb;
            }
        }
    }
}

// ============================ pad ==========================================
__global__ __launch_bounds__(256, 1) void pad_kernel(
    const float* __restrict__ bq, const float* __restrict__ bk,
    const float* __restrict__ bv)
{
    const int b = blockIdx.x;
    const int sec = blockIdx.y;
    const int tid = threadIdx.x;
    const int nf = g_cnt[b * 2];
    const int nb = g_cnt[b * 2 + 1];

    if (sec == 0) {
        const int NQ = ((nf + 64) >> 6) << 6;
        const int npad = NQ - nf;
        for (int idx = tid; idx < npad * NC; idx += 256) {
            int c = idx / npad, p = nf + idx % npad;
            g_pq[(size_t)(b * NC + c) * NPQ + p] = (p == nf) ? bq[c] : 0.f;
        }
    } else if (sec == 1) {
        const int NK = ((nb + 128) >> 7) << 7;
        const int npad = NK - nb;
        for (int idx = tid; idx < npad * NC; idx += 256) {
            int c = idx / npad, p = nb + idx % npad;
            g_pk[(size_t)(b * NC + c) * NPQ + p] = (p == nb) ? bk[c] : 0.f;
        }
    } else {
        const int NK = ((nb + 128) >> 7) << 7;
        for (int p = nb; p < NK; p++)
            g_pv[((size_t)b * NPQ + p) * NC + tid] = (p == nb) ? bv[tid] : 0.f;
    }
}

// ============================ flash attention ==============================
// 512 thr, tile 64q x 128k. S: jl=tid&15 -> j quad (jhalf*16+jl)*4,
// rowg=(tid>>4)&15 -> rows rowg*4..+3, jhalf=tid>>8. K in four 64c x 128j
// chunks (32KB). PV: c0=jl*4+jhalf*64, quads {c0, c0+128}; V in two
// 64j x 256c halves (64KB). Pool 4x32KB: K ping-pongs in two while V
// streams through the other two.
__global__ __launch_bounds__(512, 1) void attn_kernel()
{
    extern __shared__ float smf[];
    float* Qs   = smf;              // [256c][64i] 16384
    float* Pool = smf + 16384;      // 4 x 8192
    float* Ps   = smf + 49152;      // [64i][128j] 8192
    float* Red  = smf + 57344;      // 256

    const int tid   = threadIdx.x;
    const int jl    = tid & 15;
    const int rowg  = (tid >> 4) & 15;
    const int jhalf = tid >> 8;
    const int b  = blockIdx.y;
    const int i0 = blockIdx.x * 64;

    const int nf = g_cnt[b * 2];
    const int nb = g_cnt[b * 2 + 1];
    if (i0 >= nf + 1) return;
    const int nkt = (nb + 128) >> 7;
    const float wF = (float)nf;
    const int c0 = jl * 4 + jhalf * 64;

    auto PB = [&](int i) { return Pool + i * 8192; };

    auto loadK = [&](int ck, int j0, float* buf) {
        const float* src = g_pk + (size_t)(b * NC + ck * 64) * NPQ + j0;
        #pragma unroll
        for (int it = 0; it < 4; it++) {
            int idx = tid + it * 512;
            int c = idx >> 5, j4 = idx & 31;
            cp16(&buf[c * 128 + j4 * 4], &src[(size_t)c * NPQ + j4 * 4]);
        }
        CP_COMMIT;
    };
    auto loadV = [&](int vh, int j0, float* buf) {
        const float* src = g_pv + ((size_t)b * NPQ + j0 + vh * 64) * NC;
        #pragma unroll
        for (int it = 0; it < 8; it++) {
            int idx = tid + it * 512;
            int j = idx >> 6, c4 = idx & 63;
            cp16(&buf[j * 256 + c4 * 4], &src[(size_t)j * NC + c4 * 4]);
        }
        CP_COMMIT;
    };

    // prologue: Q + K chunk0 of tile 0 in one group
    #pragma unroll
    for (int it = 0; it < 8; it++) {
        int idx = tid + it * 512;
        int c = idx >> 4, i4 = idx & 15;
        cp16(&Qs[c * 64 + i4 * 4], &g_pq[(size_t)(b * NC + c) * NPQ + i0 + i4 * 4]);
    }
    loadK(0, 0, PB(0));

    float m_i[4], l_i[4];
    #pragma unroll
    for (int ii = 0; ii < 4; ii++) { m_i[ii] = -1e30f; l_i[ii] = 0.f; }
    ulonglong2 oa[2][4];
    #pragma unroll
    for (int q = 0; q < 2; q++)
        #pragma unroll
        for (int ii = 0; ii < 4; ii++) { oa[q][ii].x = 0ull; oa[q][ii].y = 0ull; }

    ull s2[2][4];

    auto sphase = [&](int p, const float* Kb) {
        const float* qb = Qs + (p * 64) * 64 + rowg * 4;
        const float* kb = Kb + (jhalf * 16 + jl) * 4;
        #pragma unroll 8
        for (int c = 0; c < 64; c++) {
            ulonglong2 q2 = *reinterpret_cast<const ulonglong2*>(qb + c * 64);
            float4 k4 = *reinterpret_cast<const float4*>(kb + c * 128);
            ull kd0 = pack2(k4.x, k4.x), kd1 = pack2(k4.y, k4.y);
            ull kd2 = pack2(k4.z, k4.z), kd3 = pack2(k4.w, k4.w);
            s2[0][0] = fma2(q2.x, kd0, s2[0][0]); s2[1][0] = fma2(q2.y, kd0, s2[1][0]);
            s2[0][1] = fma2(q2.x, kd1, s2[0][1]); s2[1][1] = fma2(q2.y, kd1, s2[1][1]);
            s2[0][2] = fma2(q2.x, kd2, s2[0][2]); s2[1][2] = fma2(q2.y, kd2, s2[1][2]);
            s2[0][3] = fma2(q2.x, kd3, s2[0][3]); s2[1][3] = fma2(q2.y, kd3, s2[1][3]);
        }
    };

    auto pvphase = [&](int jb, const float* Vb) {
        #pragma unroll 2
        for (int j4 = 0; j4 < 16; j4++) {
            float4 pr[4];
            #pragma unroll
            for (int ii = 0; ii < 4; ii++)
                pr[ii] = *reinterpret_cast<const float4*>(&Ps[(rowg * 4 + ii) * 128 + jb + j4 * 4]);
            #pragma unroll
            for (int dj = 0; dj < 4; dj++) {
                const float* vrow = Vb + (j4 * 4 + dj) * 256;
                ulonglong2 v0 = *reinterpret_cast<const ulonglong2*>(vrow + c0);
                ulonglong2 v1 = *reinterpret_cast<const ulonglong2*>(vrow + c0 + 128);
                #pragma unroll
                for (int ii = 0; ii < 4; ii++) {
                    float p = (dj == 0) ? pr[ii].x : (dj == 1) ? pr[ii].y
                            : (dj == 2) ? pr[ii].z : pr[ii].w;
                    ull pd = pack2(p, p);
                    oa[0][ii].x = fma2(v0.x, pd, oa[0][ii].x);
                    oa[0][ii].y = fma2(v0.y, pd, oa[0][ii].y);
                    oa[1][ii].x = fma2(v1.x, pd, oa[1][ii].x);
                    oa[1][ii].y = fma2(v1.y, pd, oa[1][ii].y);
                }
            }
        }
    };

    for (int jt = 0; jt < nkt; jt++) {
        const int j0 = jt << 7;
        const int kb = (jt & 1) ? 2 : 0;
        const int vb = 2 - kb;

        #pragma unroll
        for (int ip = 0; ip < 2; ip++)
            #pragma unroll
            for (int jj = 0; jj < 4; jj++) s2[ip][jj] = 0ull;

        CP_WAIT(0); __syncthreads();
        loadK(1, j0, PB(kb ^ 1));
        sphase(0, PB(kb));

        CP_WAIT(0); __syncthreads();
        loadK(2, j0, PB(kb));
        sphase(1, PB(kb ^ 1));

        CP_WAIT(0); __syncthreads();
        loadK(3, j0, PB(kb ^ 1));          // group A
        loadV(0, j0, PB(vb));              // group B -> PB(vb),PB(vb+1)
        sphase(2, PB(kb));

        CP_WAIT(1); __syncthreads();       // K3 done, V0 in flight
        sphase(3, PB(kb ^ 1));

        // ---- softmax over the 128-key tile ----
        {
            float sv[4][4];
            #pragma unroll
            for (int ip = 0; ip < 2; ip++)
                #pragma unroll
                for (int jj = 0; jj < 4; jj++) {
                    float2 u = unpack2(s2[ip][jj]);
                    sv[ip * 2 + 0][jj] = u.x;
                    sv[ip * 2 + 1][jj] = u.y;
                }
            const int jb2 = j0 + (jhalf * 16 + jl) * 4;
            float w[4];
            #pragma unroll
            for (int jj = 0; jj < 4; jj++) {
                int jg = jb2 + jj;
                w[jj] = (jg == nb) ? wF : 1.f;
                if (jg > nb) {
                    #pragma unroll
                    for (int ii = 0; ii < 4; ii++) sv[ii][jj] = -1e30f;
                }
            }
            float mloc[4];
            #pragma unroll
            for (int ii = 0; ii < 4; ii++) {
                float rm = fmaxf(fmaxf(sv[ii][0], sv[ii][1]), fmaxf(sv[ii][2], sv[ii][3]));
                #pragma unroll
                for (int off = 1; off < 16; off <<= 1)
                    rm = fmaxf(rm, __shfl_xor_sync(0xffffffffu, rm, off));
                mloc[ii] = rm;
            }
            if (jl == 0) {
                #pragma unroll
                for (int ii = 0; ii < 4; ii++)
                    Red[jhalf * 64 + rowg * 4 + ii] = mloc[ii];
            }
            __syncthreads();
            float alpha[4], rsum[4];
            #pragma unroll
            for (int ii = 0; ii < 4; ii++) {
                int row = rowg * 4 + ii;
                float mt = fmaxf(Red[row], Red[64 + row]);
                float mn = fmaxf(m_i[ii], mt);
                alpha[ii] = __expf(m_i[ii] - mn);
                m_i[ii] = mn;
                float p0 = __expf(sv[ii][0] - mn) * w[0];
                float p1 = __expf(sv[ii][1] - mn) * w[1];
                float p2 = __expf(sv[ii][2] - mn) * w[2];
                float p3 = __expf(sv[ii][3] - mn) * w[3];
                *reinterpret_cast<float4*>(&Ps[row * 128 + jhalf * 64 + jl * 4]) =
                    make_float4(p0, p1, p2, p3);
                float s = p0 + p1 + p2 + p3;
                #pragma unroll
                for (int off = 1; off < 16; off <<= 1)
                    s += __shfl_xor_sync(0xffffffffu, s, off);
                rsum[ii] = s;
            }
            if (jl == 0) {
                #pragma unroll
                for (int ii = 0; ii < 4; ii++)
                    Red[128 + jhalf * 64 + rowg * 4 + ii] = rsum[ii];
            }
            __syncthreads();
            #pragma unroll
            for (int ii = 0; ii < 4; ii++) {
                int row = rowg * 4 + ii;
                l_i[ii] = l_i[ii] * alpha[ii] + Red[128 + row] + Red[192 + row];
                ull ad = pack2(alpha[ii], alpha[ii]);
                oa[0][ii].x = mul2(oa[0][ii].x, ad);
                oa[0][ii].y = mul2(oa[0][ii].y, ad);
                oa[1][ii].x = mul2(oa[1][ii].x, ad);
                oa[1][ii].y = mul2(oa[1][ii].y, ad);
            }
        }

        CP_WAIT(0); __syncthreads();       // V0 ready; Ps visible
        loadV(1, j0, PB(kb));              // V1 -> PB(kb),PB(kb+1)
        pvphase(0, PB(vb));

        CP_WAIT(0); __syncthreads();
        {
            const int jn = (jt + 1 < nkt) ? (jt + 1) << 7 : j0;
            loadK(0, jn, PB(vb));          // next tile's K base == PB(vb)
        }
        pvphase(64, PB(kb));
    }
    CP_WAIT(0);

    float inv[4];
    #pragma unroll
    for (int ii = 0; ii < 4; ii++) inv[ii] = 1.f / l_i[ii];

    #pragma unroll
    for (int q = 0; q < 2; q++) {
        float of[4][4];
        #pragma unroll
        for (int ii = 0; ii < 4; ii++) {
            float2 u0 = unpack2(oa[q][ii].x);
            float2 u1 = unpack2(oa[q][ii].y);
            of[ii][0] = u0.x * inv[ii];
            of[ii][1] = u0.y * inv[ii];
            of[ii][2] = u1.x * inv[ii];
            of[ii][3] = u1.y * inv[ii];
        }
        #pragma unroll
        for (int d = 0; d < 4; d++) {
            int c = c0 + q * 128 + d;
            *reinterpret_cast<float4*>(&g_go[(size_t)(b * NC + c) * NPQ + i0 + rowg * 4]) =
                make_float4(of[0][d], of[1][d], of[2][d], of[3][d]);
        }
    }
}

// ============================ output projection ============================
__global__ __launch_bounds__(256, 2) void proj_kernel(
    const float* __restrict__ Wo, const float* __restrict__ bo)
{
    __shared__ float Ws[32][132];
    __shared__ float Xs[32][64];

    const int tid = threadIdx.x;
    const int tx = tid & 15;
    const int ty = tid >> 4;
    const int n0 = blockIdx.x * 64;
    const int m0 = blockIdx.y * 128;
    const int b  = blockIdx.z;

    const int nfq = g_cnt[b * 2] + 1;
    if (n0 >= nfq) return;

    ull acc[4][4];
    #pragma unroll
    for (int mp = 0; mp < 4; mp++)
        #pragma unroll
        for (int jj = 0; jj < 4; jj++) acc[mp][jj] = 0ull;

    for (int kc = 0; kc < NC; kc += 32) {
        #pragma unroll
        for (int it = 0; it < 16; it++) {
            int idx = tid + it * 256;
            int m = idx >> 5, kk = idx & 31;
            Ws[kk][m] = Wo[(m0 + m) * 256 + kc + kk];
        }
        #pragma unroll
        for (int it = 0; it < 2; it++) {
            int idx = tid + it * 256;
            int k = idx >> 4, j4 = idx & 15;
            *reinterpret_cast<float4*>(&Xs[k][j4 * 4]) =
                *reinterpret_cast<const float4*>(&g_go[(size_t)(b * NC + kc + k) * NPQ + n0 + j4 * 4]);
        }
        __syncthreads();
        #pragma unroll 8
        for (int k = 0; k < 32; k++) {
            ulonglong2 w01 = *reinterpret_cast<const ulonglong2*>(&Ws[k][ty * 8]);
            ulonglong2 w23 = *reinterpret_cast<const ulonglong2*>(&Ws[k][ty * 8 + 4]);
            float4 xv = *reinterpret_cast<const float4*>(&Xs[k][tx * 4]);
            ull wp[4] = { w01.x, w01.y, w23.x, w23.y };
            ull xd[4] = { pack2(xv.x, xv.x), pack2(xv.y, xv.y),
                          pack2(xv.z, xv.z), pack2(xv.w, xv.w) };
            #pragma unroll
            for (int mp = 0; mp < 4; mp++)
                #pragma unroll
                for (int jj = 0; jj < 4; jj++)
                    acc[mp][jj] = fma2(wp[mp], xd[jj], acc[mp][jj]);
        }
        __syncthreads();
    }

    #pragma unroll
    for (int mp = 0; mp < 4; mp++) {
        float2 u[4];
        #pragma unroll
        for (int jj = 0; jj < 4; jj++) u[jj] = unpack2(acc[mp][jj]);
        #pragma unroll
        for (int h = 0; h < 2; h++) {
            int o = m0 + ty * 8 + mp * 2 + h;
            float bb = bo[o];
            float4 r;
            r.x = (h ? u[0].y : u[0].x) + bb;
            r.y = (h ? u[1].y : u[1].x) + bb;
            r.z = (h ? u[2].y : u[2].x) + bb;
            r.w = (h ? u[3].y : u[3].x) + bb;
            *reinterpret_cast<float4*>(&g_p[(size_t)(b * NC + o) * NPQ + n0 + tx * 4]) = r;
        }
    }
}

// ============================ scatter ======================================
__global__ __launch_bounds__(256, 1) void scatter_kernel(
    const float* __restrict__ x, const float* __restrict__ gamma,
    float* __restrict__ out)
{
    const int b = blockIdx.y;
    const int n = blockIdx.x * 256 + threadIdx.x;
    const int ci = g_cidx[(size_t)b * NP + n];
    const float g0 = gamma[0];

    const float* px = x + (size_t)b * NC * NP + n;
    const float* pp = g_p + (size_t)b * NC * NPQ + ci;
    float* po = out + (size_t)b * NC * NP + n;

    #pragma unroll 4
    for (int c = 0; c < NC; c++) {
        po[(size_t)c * NP] = pp[(size_t)c * NPQ] + g0 * px[(size_t)c * NP];
    }
}

extern "C" void kernel_launch(void* const* d_in, const int* in_sizes, int n_in,
                              void* d_out, int out_size)
{
    const float* x     = (const float*)d_in[0];
    const float* mask  = (const float*)d_in[1];
    const float* Wq    = (const float*)d_in[2];
    const float* bq    = (const float*)d_in[3];
    const float* Wk    = (const float*)d_in[4];
    const float* bk    = (const float*)d_in[5];
    const float* Wv    = (const float*)d_in[6];
    const float* bv    = (const float*)d_in[7];
    const float* Wo    = (const float*)d_in[8];
    const float* bo    = (const float*)d_in[9];
    const float* gamma = (const float*)d_in[10];
    float* out = (float*)d_out;

    compact_kernel<<<NB, 256>>>(mask);
    qkv_kernel<<<dim3(64, 6, NB), 256>>>(x, mask, Wq, bq, Wk, bk, Wv, bv);
    pad_kernel<<<dim3(NB, 3), 256>>>(bq, bk, bv);

    const size_t smemB = (size_t)(16384 + 32768 + 8192 + 256) * sizeof(float);  // 230400 B
    cudaFuncSetAttribute(attn_kernel, cudaFuncAttributeMaxDynamicSharedMemorySize, (int)smemB);
    attn_kernel<<<dim3(65, NB), 512, smemB>>>();

    proj_kernel<<<dim3(65, 2, NB), 256>>>(Wo, bo);
    scatter_kernel<<<dim3(16, NB), 256>>>(x, gamma, out);
}

// round 11
// speedup vs baseline: 1.3148x; 1.3136x over previous
#include <cuda_runtime.h>
#include <cuda_bf16.h>
#include <cstdint>

#define NB 8
#define NC 256
#define NP 4096
#define NPQ 4224

typedef unsigned long long ull;
typedef __nv_bfloat16 bf16;

__device__ bf16  g_qh[NB * NPQ * NC];   // q hi [b][p][c]
__device__ bf16  g_ql[NB * NPQ * NC];
__device__ bf16  g_kh[NB * NPQ * NC];   // k hi [b][p][c]
__device__ bf16  g_kl[NB * NPQ * NC];
__device__ bf16  g_vh[NB * NC * NPQ];   // v hi [b][c][p]
__device__ bf16  g_vl[NB * NC * NPQ];
__device__ float g_go[NB * NC * NPQ];   // attn out [b][c][p]
__device__ float g_p [NB * NC * NPQ];
__device__ int   g_pr[NB * NP];
__device__ int   g_cidx[NB * NP];
__device__ int   g_cnt[NB * 2];

__device__ __forceinline__ ull pack2(float lo, float hi) {
    ull r; asm("mov.b64 %0, {%1, %2};" : "=l"(r) : "f"(lo), "f"(hi)); return r;
}
__device__ __forceinline__ float2 unpack2(ull v) {
    float2 r; asm("mov.b64 {%0, %1}, %2;" : "=f"(r.x), "=f"(r.y) : "l"(v)); return r;
}
__device__ __forceinline__ ull fma2(ull a, ull b, ull c) {
    ull d; asm("fma.rn.f32x2 %0, %1, %2, %3;" : "=l"(d) : "l"(a), "l"(b), "l"(c)); return d;
}
__device__ __forceinline__ void cp16(void* dst, const void* src) {
    unsigned s = (unsigned)__cvta_generic_to_shared(dst);
    asm volatile("cp.async.cg.shared.global [%0], [%1], 16;" :: "r"(s), "l"(src));
}
__device__ __forceinline__ void cp4(void* dst, const void* src) {
    unsigned s = (unsigned)__cvta_generic_to_shared(dst);
    asm volatile("cp.async.ca.shared.global [%0], [%1], 4;" :: "r"(s), "l"(src));
}
#define CP_COMMIT asm volatile("cp.async.commit_group;" ::: "memory")
#define CP_WAIT(n) asm volatile("cp.async.wait_group %0;" :: "n"(n) : "memory")

__device__ __forceinline__ void bfsplit(float x, bf16& h, bf16& l) {
    h = __float2bfloat16(x);
    l = __float2bfloat16(x - __bfloat162float(h));
}
__device__ __forceinline__ void split2(float a, float b, uint32_t& h, uint32_t& l) {
    bf16 ah, al, bh, bl;
    bfsplit(a, ah, al); bfsplit(b, bh, bl);
    h = (uint32_t)__bfloat16_as_ushort(ah) | ((uint32_t)__bfloat16_as_ushort(bh) << 16);
    l = (uint32_t)__bfloat16_as_ushort(al) | ((uint32_t)__bfloat16_as_ushort(bl) << 16);
}
__device__ __forceinline__ void ldsm4(uint32_t* r, uint32_t a) {
    asm volatile("ldmatrix.sync.aligned.m8n8.x4.shared.b16 {%0,%1,%2,%3}, [%4];"
        : "=r"(r[0]), "=r"(r[1]), "=r"(r[2]), "=r"(r[3]) : "r"(a));
}
__device__ __forceinline__ void mma16816(float* d, const uint32_t* a, const uint32_t* b) {
    asm volatile("mma.sync.aligned.m16n8k16.row.col.f32.bf16.bf16.f32 "
        "{%0,%1,%2,%3},{%4,%5,%6,%7},{%8,%9},{%0,%1,%2,%3};"
        : "+f"(d[0]), "+f"(d[1]), "+f"(d[2]), "+f"(d[3])
        : "r"(a[0]), "r"(a[1]), "r"(a[2]), "r"(a[3]), "r"(b[0]), "r"(b[1]));
}

// ============================ compaction ===================================
__global__ __launch_bounds__(256, 1) void compact_kernel(const float* __restrict__ mask)
{
    const int b = blockIdx.x, tid = threadIdx.x;
    const int lane = tid & 31, wid = tid >> 5;
    __shared__ int wsum[8];
    __shared__ int s_nf;
    bool f[16]; int c = 0;
    const float* mb = mask + (size_t)b * NP;
    #pragma unroll
    for (int i = 0; i < 16; i++) { f[i] = mb[tid * 16 + i] > 0.5f; c += f[i]; }
    int v = c;
    #pragma unroll
    for (int off = 1; off < 32; off <<= 1) {
        int u = __shfl_up_sync(0xffffffffu, v, off);
        if (lane >= off) v += u;
    }
    if (lane == 31) wsum[wid] = v;
    __syncthreads();
    if (tid < 8) {
        int wv = wsum[tid];
        #pragma unroll
        for (int off = 1; off < 8; off <<= 1) {
            int u = __shfl_up_sync(0xffu, wv, off);
            if (tid >= off) wv += u;
        }
        wsum[tid] = wv;
        if (tid == 7) s_nf = wv;
    }
    __syncthreads();
    const int nf = s_nf;
    int excl = v - c + (wid ? wsum[wid - 1] : 0);
    int fo = excl, bo = tid * 16 - excl;
    int* pr = g_pr + (size_t)b * NP;
    int* cidx = g_cidx + (size_t)b * NP;
    #pragma unroll
    for (int i = 0; i < 16; i++) {
        int n = tid * 16 + i;
        if (f[i]) { pr[n] = fo; cidx[n] = fo; fo++; }
        else      { pr[n] = bo; cidx[n] = nf; bo++; }
    }
    if (tid == 0) { g_cnt[b * 2] = nf; g_cnt[b * 2 + 1] = NP - nf; }
}

// ============================ QKV projection ===============================
__global__ __launch_bounds__(256, 2) void qkv_kernel(
    const float* __restrict__ x, const float* __restrict__ mask,
    const float* __restrict__ Wq, const float* __restrict__ bq,
    const float* __restrict__ Wk, const float* __restrict__ bk,
    const float* __restrict__ Wv, const float* __restrict__ bv)
{
    __shared__ float Ws[2][32][132];
    __shared__ float Xs[2][32][64];
    const int tid = threadIdx.x;
    const int tx = tid & 15, ty = tid >> 4;
    const int n0 = blockIdx.x * 64, m0 = blockIdx.y * 128, b = blockIdx.z;

    ull acc[4][4];
    #pragma unroll
    for (int mp = 0; mp < 4; mp++)
        #pragma unroll
        for (int jj = 0; jj < 4; jj++) acc[mp][jj] = 0ull;

    auto issue = [&](int ci, int buf) {
        const int kc = ci * 32;
        #pragma unroll
        for (int it = 0; it < 16; it++) {
            int idx = tid + it * 256;
            int m = idx >> 5, kk = idx & 31;
            int mg = m0 + m;
            const float* Wp = (mg < 256) ? Wq : ((mg < 512) ? Wk : Wv);
            cp4(&Ws[buf][kk][m], &Wp[(mg & 255) * 256 + kc + kk]);
        }
        #pragma unroll
        for (int it = 0; it < 2; it++) {
            int idx = tid + it * 256;
            int k = idx >> 4, j4 = idx & 15;
            cp16(&Xs[buf][k][j4 * 4], &x[(size_t)(b * NC + kc + k) * NP + n0 + j4 * 4]);
        }
        CP_COMMIT;
    };

    issue(0, 0);
    for (int ci = 0; ci < 8; ci++) {
        int nxt = (ci + 1 < 8) ? ci + 1 : 7;
        issue(nxt, (ci + 1) & 1);
        CP_WAIT(1);
        __syncthreads();
        const int buf = ci & 1;
        #pragma unroll 8
        for (int k = 0; k < 32; k++) {
            ulonglong2 w01 = *reinterpret_cast<const ulonglong2*>(&Ws[buf][k][ty * 8]);
            ulonglong2 w23 = *reinterpret_cast<const ulonglong2*>(&Ws[buf][k][ty * 8 + 4]);
            float4 xv = *reinterpret_cast<const float4*>(&Xs[buf][k][tx * 4]);
            ull wp[4] = { w01.x, w01.y, w23.x, w23.y };
            ull xd[4] = { pack2(xv.x, xv.x), pack2(xv.y, xv.y),
                          pack2(xv.z, xv.z), pack2(xv.w, xv.w) };
            #pragma unroll
            for (int mp = 0; mp < 4; mp++)
                #pragma unroll
                for (int jj = 0; jj < 4; jj++)
                    acc[mp][jj] = fma2(wp[mp], xd[jj], acc[mp][jj]);
        }
        __syncthreads();
    }
    CP_WAIT(0);

    const int sel = m0 >> 8;
    const int nbase = n0 + tx * 4;
    float mk[4]; int pr[4];
    #pragma unroll
    for (int jj = 0; jj < 4; jj++) {
        mk[jj] = mask[(size_t)b * NP + nbase + jj];
        pr[jj] = g_pr[(size_t)b * NP + nbase + jj];
    }
    #pragma unroll
    for (int mp = 0; mp < 4; mp++) {
        float2 u[4];
        #pragma unroll
        for (int jj = 0; jj < 4; jj++) u[jj] = unpack2(acc[mp][jj]);
        #pragma unroll
        for (int h = 0; h < 2; h++) {
            const int o = (m0 & 255) + ty * 8 + mp * 2 + h;
            float val[4];
            val[0] = h ? u[0].y : u[0].x; val[1] = h ? u[1].y : u[1].x;
            val[2] = h ? u[2].y : u[2].x; val[3] = h ? u[3].y : u[3].x;
            if (sel == 0) {
                const float bb = bq[o];
                #pragma unroll
                for (int jj = 0; jj < 4; jj++)
                    if (mk[jj] > 0.5f) {
                        bf16 hh, ll; bfsplit(val[jj] + bb, hh, ll);
                        size_t off = ((size_t)b * NPQ + pr[jj]) * NC + o;
                        g_qh[off] = hh; g_ql[off] = ll;
                    }
            } else if (sel == 1) {
                const float bb = bk[o];
                #pragma unroll
                for (int jj = 0; jj < 4; jj++)
                    if (mk[jj] < 0.5f) {
                        bf16 hh, ll; bfsplit(val[jj] + bb, hh, ll);
                        size_t off = ((size_t)b * NPQ + pr[jj]) * NC + o;
                        g_kh[off] = hh; g_kl[off] = ll;
                    }
            } else {
                const float bb = bv[o];
                #pragma unroll
                for (int jj = 0; jj < 4; jj++)
                    if (mk[jj] < 0.5f) {
                        bf16 hh, ll; bfsplit(val[jj] + bb, hh, ll);
                        size_t off = ((size_t)b * NC + o) * NPQ + pr[jj];
                        g_vh[off] = hh; g_vl[off] = ll;
                    }
            }
        }
    }
}

// ============================ pad ==========================================
__global__ __launch_bounds__(256, 1) void pad_kernel(
    const float* __restrict__ bq, const float* __restrict__ bk,
    const float* __restrict__ bv)
{
    const int b = blockIdx.x, sec = blockIdx.y, tid = threadIdx.x;
    const int nf = g_cnt[b * 2], nb = g_cnt[b * 2 + 1];
    if (sec == 0) {
        const int NQ = ((nf + 64) >> 6) << 6;
        const int tot = (NQ - nf) * NC;
        for (int idx = tid; idx < tot; idx += 256) {
            int p = nf + (idx >> 8), c = idx & 255;
            bf16 h(__float2bfloat16(0.f)), l(__float2bfloat16(0.f));
            if (p == nf) bfsplit(bq[c], h, l);
            size_t off = ((size_t)b * NPQ + p) * NC + c;
            g_qh[off] = h; g_ql[off] = l;
        }
    } else if (sec == 1) {
        const int NK = ((nb + 128) >> 7) << 7;
        const int tot = (NK - nb) * NC;
        for (int idx = tid; idx < tot; idx += 256) {
            int p = nb + (idx >> 8), c = idx & 255;
            bf16 h(__float2bfloat16(0.f)), l(__float2bfloat16(0.f));
            if (p == nb) bfsplit(bk[c], h, l);
            size_t off = ((size_t)b * NPQ + p) * NC + c;
            g_kh[off] = h; g_kl[off] = l;
        }
    } else {
        const int NK = ((nb + 128) >> 7) << 7;
        for (int p = nb; p < NK; p++) {
            bf16 h(__float2bfloat16(0.f)), l(__float2bfloat16(0.f));
            if (p == nb) bfsplit(bv[tid], h, l);
            size_t off = ((size_t)b * NC + tid) * NPQ + p;
            g_vh[off] = h; g_vl[off] = l;
        }
    }
}

// ============================ flash attention (mma.sync bf16) ==============
// 512 thr = 16 warps (wr=wid&3 row strip of 16 q, wc=wid>>2 col strip).
// Tile 64q x 128k. S: A=Q[i][c] (resident), B=K[j][c] chunks (64c) non-trans
// ldmatrix. PV: A=P[i][j] smem, B=V[c][j] chunks (64c). 3-term bf16 split.
// smem swizzle: byte ^ ((row&7)<<4). Pool ring of 4 x 32KB, 8 phases/tile.
__global__ __launch_bounds__(512, 1) void attn_kernel()
{
    extern __shared__ char smc[];
    char* Pool = smc + 65536;
    char* Psh  = smc + 196608;
    char* Psl  = smc + 212992;
    float* Red = (float*)(smc + 229376);
    float* m_s = Red; float* l_s = Red + 64; float* A_s = Red + 128;
    float* Rmax = Red + 192; float* Rsum = Red + 448;

    const uint32_t sb = (uint32_t)__cvta_generic_to_shared(smc);
    const uint32_t qh_b = sb, ql_b = sb + 32768;
    const uint32_t pool_b = sb + 65536;
    const uint32_t psh_b = sb + 196608, psl_b = sb + 212992;

    const int tid = threadIdx.x, lane = tid & 31, wid = tid >> 5;
    const int wr = wid & 3, wc = wid >> 2;
    const int tq = lane >> 2, tr = lane & 3;
    const int b = blockIdx.y, i0 = blockIdx.x * 64;

    const int nf = g_cnt[b * 2], nb = g_cnt[b * 2 + 1];
    if (i0 >= nf + 1) return;
    const int nkt = (nb + 128) >> 7;
    const float wF = (float)nf;
    const int r0 = 16 * wr + tq, r1 = r0 + 8;

    auto loadK = [&](int ck, int j0, char* buf) {
        #pragma unroll
        for (int it = 0; it < 2; it++) {
            int idx = tid + it * 512;
            int j = idx >> 3, c16 = idx & 7;
            uint32_t d = j * 128 + ((c16 * 16) ^ ((j & 7) << 4));
            size_t s = ((size_t)b * NPQ + j0 + j) * NC + ck * 64 + c16 * 8;
            cp16(buf + d, g_kh + s);
            cp16(buf + 16384 + d, g_kl + s);
        }
        CP_COMMIT;
    };
    auto loadV = [&](int cc, int j0, char* buf) {
        #pragma unroll
        for (int it = 0; it < 2; it++) {
            int idx = tid + it * 512;
            int c = idx >> 4, j16 = idx & 15;
            uint32_t d = c * 256 + ((j16 * 16) ^ ((c & 7) << 4));
            size_t s = ((size_t)b * NC + cc * 64 + c) * NPQ + j0 + j16 * 8;
            cp16(buf + d, g_vh + s);
            cp16(buf + 16384 + d, g_vl + s);
        }
        CP_COMMIT;
    };

    // prologue: Q (h+l) + K chunk0 in group1; K chunk1 in group2
    #pragma unroll
    for (int it = 0; it < 4; it++) {
        int idx = tid + it * 512;
        int i = idx >> 5, c16 = idx & 31;
        uint32_t d = i * 512 + ((c16 * 16) ^ ((i & 7) << 4));
        size_t s = ((size_t)b * NPQ + i0 + i) * NC + c16 * 8;
        cp16(smc + d, g_qh + s);
        cp16(smc + 32768 + d, g_ql + s);
    }
    loadK(0, 0, Pool);
    loadK(1, 0, Pool + 32768);

    if (tid < 64) { m_s[tid] = -1e30f; l_s[tid] = 0.f; }

    float sacc[4][4];
    float oa[4][2][4];
    #pragma unroll
    for (int cc = 0; cc < 4; cc++)
        #pragma unroll
        for (int nt = 0; nt < 2; nt++)
            #pragma unroll
            for (int d = 0; d < 4; d++) oa[cc][nt][d] = 0.f;

    const int qtot = nkt * 8;
    for (int q = 0; q < qtot; q++) {
        CP_WAIT(1);
        __syncthreads();
        const int q2 = q + 2;
        if (q2 < qtot) {
            char* buf2 = Pool + (q2 & 3) * 32768;
            int jt2 = q2 >> 3, ph2 = q2 & 7;
            if (ph2 < 4) loadK(ph2, jt2 << 7, buf2);
            else loadV(ph2 - 4, jt2 << 7, buf2);
        } else CP_COMMIT;

        const int ph = q & 7, jt = q >> 3;
        const uint32_t bufb = pool_b + (q & 3) * 32768;

        if (ph < 4) {
            if (ph == 0) {
                #pragma unroll
                for (int nt = 0; nt < 4; nt++)
                    #pragma unroll
                    for (int d = 0; d < 4; d++) sacc[nt][d] = 0.f;
            }
            // ---- S chunk: c in [ph*64, ph*64+64) ----
            const int ai = 16 * wr + (lane & 15);
            const int bj = 32 * wc + (lane & 7) + ((lane >> 4) << 3);
            const int bj1 = bj + 16;
            #pragma unroll
            for (int kc = 0; kc < 4; kc++) {
                uint32_t abyte = ai * 512 +
                    ((((ph * 64 + kc * 16) * 2) + (lane >> 4) * 16) ^ ((ai & 7) << 4));
                uint32_t ah[4], al[4];
                ldsm4(ah, qh_b + abyte);
                ldsm4(al, ql_b + abyte);
                uint32_t bbyte = kc * 32 + ((lane >> 3) & 1) * 16;
                uint32_t ka0 = bufb + bj * 128 + (bbyte ^ ((bj & 7) << 4));
                uint32_t ka1 = bufb + bj1 * 128 + (bbyte ^ ((bj1 & 7) << 4));
                uint32_t bh0[4], bl0[4], bh1[4], bl1[4];
                ldsm4(bh0, ka0); ldsm4(bl0, ka0 + 16384);
                ldsm4(bh1, ka1); ldsm4(bl1, ka1 + 16384);
                mma16816(sacc[0], ah, bh0);     mma16816(sacc[0], ah, bl0);     mma16816(sacc[0], al, bh0);
                mma16816(sacc[1], ah, bh0 + 2); mma16816(sacc[1], ah, bl0 + 2); mma16816(sacc[1], al, bh0 + 2);
                mma16816(sacc[2], ah, bh1);     mma16816(sacc[2], ah, bl1);     mma16816(sacc[2], al, bh1);
                mma16816(sacc[3], ah, bh1 + 2); mma16816(sacc[3], ah, bl1 + 2); mma16816(sacc[3], al, bh1 + 2);
            }
        } else {
            if (ph == 4) {
                // ---- softmax over this 128-key tile ----
                const int j0 = jt << 7;
                float mx0 = -1e30f, mx1 = -1e30f;
                #pragma unroll
                for (int nt = 0; nt < 4; nt++)
                    #pragma unroll
                    for (int e = 0; e < 2; e++) {
                        int jg = j0 + 32 * wc + 8 * nt + 2 * tr + e;
                        if (jg > nb) { sacc[nt][e] = -1e30f; sacc[nt][2 + e] = -1e30f; }
                        mx0 = fmaxf(mx0, sacc[nt][e]);
                        mx1 = fmaxf(mx1, sacc[nt][2 + e]);
                    }
                #pragma unroll
                for (int off = 1; off < 4; off <<= 1) {
                    mx0 = fmaxf(mx0, __shfl_xor_sync(0xffffffffu, mx0, off));
                    mx1 = fmaxf(mx1, __shfl_xor_sync(0xffffffffu, mx1, off));
                }
                if (tr == 0) { Rmax[wc * 64 + r0] = mx0; Rmax[wc * 64 + r1] = mx1; }
                __syncthreads();
                if (tid < 64) {
                    float mt = fmaxf(fmaxf(Rmax[tid], Rmax[64 + tid]),
                                     fmaxf(Rmax[128 + tid], Rmax[192 + tid]));
                    float mo = m_s[tid];
                    float mn = fmaxf(mo, mt);
                    m_s[tid] = mn;
                    A_s[tid] = __expf(mo - mn);
                }
                __syncthreads();
                const float mn0 = m_s[r0], mn1 = m_s[r1];
                const float a0 = A_s[r0], a1 = A_s[r1];
                #pragma unroll
                for (int cc = 0; cc < 4; cc++)
                    #pragma unroll
                    for (int nt = 0; nt < 2; nt++) {
                        oa[cc][nt][0] *= a0; oa[cc][nt][1] *= a0;
                        oa[cc][nt][2] *= a1; oa[cc][nt][3] *= a1;
                    }
                float sm0 = 0.f, sm1 = 0.f;
                #pragma unroll
                for (int nt = 0; nt < 4; nt++) {
                    int jg0 = j0 + 32 * wc + 8 * nt + 2 * tr;
                    float w0 = (jg0 == nb) ? wF : 1.f;
                    float w1 = (jg0 + 1 == nb) ? wF : 1.f;
                    float p00 = __expf(sacc[nt][0] - mn0) * w0;
                    float p01 = __expf(sacc[nt][1] - mn0) * w1;
                    float p10 = __expf(sacc[nt][2] - mn1) * w0;
                    float p11 = __expf(sacc[nt][3] - mn1) * w1;
                    sm0 += p00 + p01; sm1 += p10 + p11;
                    uint32_t h, l;
                    int colb = (32 * wc + 8 * nt + 2 * tr) * 2;
                    split2(p00, p01, h, l);
                    *(uint32_t*)(Psh + r0 * 256 + (colb ^ ((r0 & 7) << 4))) = h;
                    *(uint32_t*)(Psl + r0 * 256 + (colb ^ ((r0 & 7) << 4))) = l;
                    split2(p10, p11, h, l);
                    *(uint32_t*)(Psh + r1 * 256 + (colb ^ ((r1 & 7) << 4))) = h;
                    *(uint32_t*)(Psl + r1 * 256 + (colb ^ ((r1 & 7) << 4))) = l;
                }
                #pragma unroll
                for (int off = 1; off < 4; off <<= 1) {
                    sm0 += __shfl_xor_sync(0xffffffffu, sm0, off);
                    sm1 += __shfl_xor_sync(0xffffffffu, sm1, off);
                }
                if (tr == 0) { Rsum[wc * 64 + r0] = sm0; Rsum[wc * 64 + r1] = sm1; }
                __syncthreads();
                if (tid < 64)
                    l_s[tid] = l_s[tid] * A_s[tid] +
                        Rsum[tid] + Rsum[64 + tid] + Rsum[128 + tid] + Rsum[192 + tid];
            }
            // ---- PV chunk cc = ph-4: cols c in [cc*64, cc*64+64) ----
            const int cc = ph - 4;
            const int ai = 16 * wr + (lane & 15);
            const int cn = 16 * wc + (lane & 7) + ((lane >> 4) << 3);
            #pragma unroll
            for (int jc = 0; jc < 8; jc++) {
                uint32_t abyte = ai * 256 + ((jc * 32 + (lane >> 4) * 16) ^ ((ai & 7) << 4));
                uint32_t ph4[4], pl4[4];
                ldsm4(ph4, psh_b + abyte);
                ldsm4(pl4, psl_b + abyte);
                uint32_t bbyte = jc * 32 + ((lane >> 3) & 1) * 16;
                uint32_t va = bufb + cn * 256 + (bbyte ^ ((cn & 7) << 4));
                uint32_t vh4[4], vl4[4];
                ldsm4(vh4, va); ldsm4(vl4, va + 16384);
                mma16816(oa[cc][0], ph4, vh4);     mma16816(oa[cc][0], ph4, vl4);     mma16816(oa[cc][0], pl4, vh4);
                mma16816(oa[cc][1], ph4, vh4 + 2); mma16816(oa[cc][1], ph4, vl4 + 2); mma16816(oa[cc][1], pl4, vh4 + 2);
            }
        }
    }
    CP_WAIT(0);
    __syncthreads();

    const float inv0 = 1.f / l_s[r0], inv1 = 1.f / l_s[r1];
    #pragma unroll
    for (int cc = 0; cc < 4; cc++)
        #pragma unroll
        for (int nt = 0; nt < 2; nt++) {
            int c = 64 * cc + 16 * wc + 8 * nt + 2 * tr;
            float* d0 = &g_go[(size_t)(b * NC + c) * NPQ + i0];
            float* d1 = &g_go[(size_t)(b * NC + c + 1) * NPQ + i0];
            d0[r0] = oa[cc][nt][0] * inv0;
            d1[r0] = oa[cc][nt][1] * inv0;
            d0[r1] = oa[cc][nt][2] * inv1;
            d1[r1] = oa[cc][nt][3] * inv1;
        }
}

// ============================ output projection ============================
__global__ __launch_bounds__(256, 2) void proj_kernel(
    const float* __restrict__ Wo, const float* __restrict__ bo)
{
    __shared__ float Ws[32][132];
    __shared__ float Xs[32][64];
    const int tid = threadIdx.x;
    const int tx = tid & 15, ty = tid >> 4;
    const int n0 = blockIdx.x * 64, m0 = blockIdx.y * 128, b = blockIdx.z;
    const int nfq = g_cnt[b * 2] + 1;
    if (n0 >= nfq) return;

    ull acc[4][4];
    #pragma unroll
    for (int mp = 0; mp < 4; mp++)
        #pragma unroll
        for (int jj = 0; jj < 4; jj++) acc[mp][jj] = 0ull;

    for (int kc = 0; kc < NC; kc += 32) {
        #pragma unroll
        for (int it = 0; it < 16; it++) {
            int idx = tid + it * 256;
            int m = idx >> 5, kk = idx & 31;
            Ws[kk][m] = Wo[(m0 + m) * 256 + kc + kk];
        }
        #pragma unroll
        for (int it = 0; it < 2; it++) {
            int idx = tid + it * 256;
            int k = idx >> 4, j4 = idx & 15;
            *reinterpret_cast<float4*>(&Xs[k][j4 * 4]) =
                *reinterpret_cast<const float4*>(&g_go[(size_t)(b * NC + kc + k) * NPQ + n0 + j4 * 4]);
        }
        __syncthreads();
        #pragma unroll 8
        for (int k = 0; k < 32; k++) {
            ulonglong2 w01 = *reinterpret_cast<const ulonglong2*>(&Ws[k][ty * 8]);
            ulonglong2 w23 = *reinterpret_cast<const ulonglong2*>(&Ws[k][ty * 8 + 4]);
            float4 xv = *reinterpret_cast<const float4*>(&Xs[k][tx * 4]);
            ull wp[4] = { w01.x, w01.y, w23.x, w23.y };
            ull xd[4] = { pack2(xv.x, xv.x), pack2(xv.y, xv.y),
                          pack2(xv.z, xv.z), pack2(xv.w, xv.w) };
            #pragma unroll
            for (int mp = 0; mp < 4; mp++)
                #pragma unroll
                for (int jj = 0; jj < 4; jj++)
                    acc[mp][jj] = fma2(wp[mp], xd[jj], acc[mp][jj]);
        }
        __syncthreads();
    }

    #pragma unroll
    for (int mp = 0; mp < 4; mp++) {
        float2 u[4];
        #pragma unroll
        for (int jj = 0; jj < 4; jj++) u[jj] = unpack2(acc[mp][jj]);
        #pragma unroll
        for (int h = 0; h < 2; h++) {
            int o = m0 + ty * 8 + mp * 2 + h;
            float bb = bo[o];
            float4 r;
            r.x = (h ? u[0].y : u[0].x) + bb;
            r.y = (h ? u[1].y : u[1].x) + bb;
            r.z = (h ? u[2].y : u[2].x) + bb;
            r.w = (h ? u[3].y : u[3].x) + bb;
            *reinterpret_cast<float4*>(&g_p[(size_t)(b * NC + o) * NPQ + n0 + tx * 4]) = r;
        }
    }
}

// ============================ scatter ======================================
__global__ __launch_bounds__(256, 1) void scatter_kernel(
    const float* __restrict__ x, const float* __restrict__ gamma,
    float* __restrict__ out)
{
    const int b = blockIdx.y;
    const int n = blockIdx.x * 256 + threadIdx.x;
    const int ci = g_cidx[(size_t)b * NP + n];
    const float g0 = gamma[0];
    const float* px = x + (size_t)b * NC * NP + n;
    const float* pp = g_p + (size_t)b * NC * NPQ + ci;
    float* po = out + (size_t)b * NC * NP + n;
    #pragma unroll 4
    for (int c = 0; c < NC; c++)
        po[(size_t)c * NP] = pp[(size_t)c * NPQ] + g0 * px[(size_t)c * NP];
}

extern "C" void kernel_launch(void* const* d_in, const int* in_sizes, int n_in,
                              void* d_out, int out_size)
{
    const float* x     = (const float*)d_in[0];
    const float* mask  = (const float*)d_in[1];
    const float* Wq    = (const float*)d_in[2];
    const float* bq    = (const float*)d_in[3];
    const float* Wk    = (const float*)d_in[4];
    const float* bk    = (const float*)d_in[5];
    const float* Wv    = (const float*)d_in[6];
    const float* bv    = (const float*)d_in[7];
    const float* Wo    = (const float*)d_in[8];
    const float* bo    = (const float*)d_in[9];
    const float* gamma = (const float*)d_in[10];
    float* out = (float*)d_out;

    compact_kernel<<<NB, 256>>>(mask);
    qkv_kernel<<<dim3(64, 6, NB), 256>>>(x, mask, Wq, bq, Wk, bk, Wv, bv);
    pad_kernel<<<dim3(NB, 3), 256>>>(bq, bk, bv);

    const size_t smemB = 232192;   // 64K Q + 128K pool + 32K Ps + red
    cudaFuncSetAttribute(attn_kernel, cudaFuncAttributeMaxDynamicSharedMemorySize, (int)smemB);
    attn_kernel<<<dim3(65, NB), 512, smemB>>>();

    proj_kernel<<<dim3(65, 2, NB), 256>>>(Wo, bo);
    scatter_kernel<<<dim3(16, NB), 256>>>(x, gamma, out);
}

// round 12
// speedup vs baseline: 1.5596x; 1.1862x over previous
#include <cuda_runtime.h>
#include <cuda_bf16.h>
#include <cstdint>

#define NB 8
#define NC 256
#define NP 4096
#define NPQ 4224

typedef unsigned long long ull;
typedef __nv_bfloat16 bf16;

__device__ bf16  g_qh[NB * NPQ * NC];   // q hi [b][p][c]
__device__ bf16  g_ql[NB * NPQ * NC];
__device__ bf16  g_kh[NB * NPQ * NC];   // k hi [b][p][c]
__device__ bf16  g_kl[NB * NPQ * NC];
__device__ bf16  g_vh[NB * NC * NPQ];   // v hi [b][c][p]
__device__ bf16  g_vl[NB * NC * NPQ];
__device__ bf16  g_wh[768 * 256];       // stacked Wq/Wk/Wv hi [o][c]
__device__ bf16  g_wl[768 * 256];
__device__ bf16  g_xh[NB * NC * NP];    // x hi [b][c][n]
__device__ bf16  g_xl[NB * NC * NP];
__device__ float g_go[NB * NC * NPQ];   // attn out [b][c][p]
__device__ float g_p [NB * NC * NPQ];
__device__ int   g_pr[NB * NP];
__device__ int   g_cidx[NB * NP];
__device__ int   g_cnt[NB * 2];

__device__ __forceinline__ ull pack2(float lo, float hi) {
    ull r; asm("mov.b64 %0, {%1, %2};" : "=l"(r) : "f"(lo), "f"(hi)); return r;
}
__device__ __forceinline__ float2 unpack2(ull v) {
    float2 r; asm("mov.b64 {%0, %1}, %2;" : "=f"(r.x), "=f"(r.y) : "l"(v)); return r;
}
__device__ __forceinline__ ull fma2(ull a, ull b, ull c) {
    ull d; asm("fma.rn.f32x2 %0, %1, %2, %3;" : "=l"(d) : "l"(a), "l"(b), "l"(c)); return d;
}
__device__ __forceinline__ void cp16(void* dst, const void* src) {
    unsigned s = (unsigned)__cvta_generic_to_shared(dst);
    asm volatile("cp.async.cg.shared.global [%0], [%1], 16;" :: "r"(s), "l"(src));
}
#define CP_COMMIT asm volatile("cp.async.commit_group;" ::: "memory")
#define CP_WAIT(n) asm volatile("cp.async.wait_group %0;" :: "n"(n) : "memory")

__device__ __forceinline__ void bfsplit(float x, bf16& h, bf16& l) {
    h = __float2bfloat16(x);
    l = __float2bfloat16(x - __bfloat162float(h));
}
__device__ __forceinline__ void split2(float a, float b, uint32_t& h, uint32_t& l) {
    bf16 ah, al, bh, bl;
    bfsplit(a, ah, al); bfsplit(b, bh, bl);
    h = (uint32_t)__bfloat16_as_ushort(ah) | ((uint32_t)__bfloat16_as_ushort(bh) << 16);
    l = (uint32_t)__bfloat16_as_ushort(al) | ((uint32_t)__bfloat16_as_ushort(bl) << 16);
}
__device__ __forceinline__ void ldsm4(uint32_t* r, uint32_t a) {
    asm volatile("ldmatrix.sync.aligned.m8n8.x4.shared.b16 {%0,%1,%2,%3}, [%4];"
        : "=r"(r[0]), "=r"(r[1]), "=r"(r[2]), "=r"(r[3]) : "r"(a));
}
__device__ __forceinline__ void ldsm4t(uint32_t* r, uint32_t a) {
    asm volatile("ldmatrix.sync.aligned.m8n8.x4.trans.shared.b16 {%0,%1,%2,%3}, [%4];"
        : "=r"(r[0]), "=r"(r[1]), "=r"(r[2]), "=r"(r[3]) : "r"(a));
}
__device__ __forceinline__ void mma16816(float* d, const uint32_t* a, const uint32_t* b) {
    asm volatile("mma.sync.aligned.m16n8k16.row.col.f32.bf16.bf16.f32 "
        "{%0,%1,%2,%3},{%4,%5,%6,%7},{%8,%9},{%0,%1,%2,%3};"
        : "+f"(d[0]), "+f"(d[1]), "+f"(d[2]), "+f"(d[3])
        : "r"(a[0]), "r"(a[1]), "r"(a[2]), "r"(a[3]), "r"(b[0]), "r"(b[1]));
}

// ============================ compaction ===================================
__global__ __launch_bounds__(256, 1) void compact_kernel(const float* __restrict__ mask)
{
    const int b = blockIdx.x, tid = threadIdx.x;
    const int lane = tid & 31, wid = tid >> 5;
    __shared__ int wsum[8];
    __shared__ int s_nf;
    bool f[16]; int c = 0;
    const float* mb = mask + (size_t)b * NP;
    #pragma unroll
    for (int i = 0; i < 16; i++) { f[i] = mb[tid * 16 + i] > 0.5f; c += f[i]; }
    int v = c;
    #pragma unroll
    for (int off = 1; off < 32; off <<= 1) {
        int u = __shfl_up_sync(0xffffffffu, v, off);
        if (lane >= off) v += u;
    }
    if (lane == 31) wsum[wid] = v;
    __syncthreads();
    if (tid < 8) {
        int wv = wsum[tid];
        #pragma unroll
        for (int off = 1; off < 8; off <<= 1) {
            int u = __shfl_up_sync(0xffu, wv, off);
            if (tid >= off) wv += u;
        }
        wsum[tid] = wv;
        if (tid == 7) s_nf = wv;
    }
    __syncthreads();
    const int nf = s_nf;
    int excl = v - c + (wid ? wsum[wid - 1] : 0);
    int fo = excl, bo = tid * 16 - excl;
    int* pr = g_pr + (size_t)b * NP;
    int* cidx = g_cidx + (size_t)b * NP;
    #pragma unroll
    for (int i = 0; i < 16; i++) {
        int n = tid * 16 + i;
        if (f[i]) { pr[n] = fo; cidx[n] = fo; fo++; }
        else      { pr[n] = bo; cidx[n] = nf; bo++; }
    }
    if (tid == 0) { g_cnt[b * 2] = nf; g_cnt[b * 2 + 1] = NP - nf; }
}

// ============================ W / x bf16 split prep ========================
__global__ __launch_bounds__(256, 4) void wsplit_kernel(
    const float* __restrict__ Wq, const float* __restrict__ Wk,
    const float* __restrict__ Wv)
{
    const int row = blockIdx.x;        // 0..767
    const int c = threadIdx.x;         // 0..255
    const float* W = (row < 256) ? Wq : ((row < 512) ? Wk : Wv);
    bf16 h, l; bfsplit(W[(row & 255) * 256 + c], h, l);
    g_wh[row * 256 + c] = h;
    g_wl[row * 256 + c] = l;
}

__global__ __launch_bounds__(256, 4) void xsplit_kernel(const float* __restrict__ x)
{
    const size_t i = ((size_t)blockIdx.x * 256 + threadIdx.x) * 4;
    float4 v = *reinterpret_cast<const float4*>(x + i);
    uint32_t h0, l0, h1, l1;
    split2(v.x, v.y, h0, l0);
    split2(v.z, v.w, h1, l1);
    *reinterpret_cast<uint2*>(g_xh + i) = make_uint2(h0, h1);
    *reinterpret_cast<uint2*>(g_xl + i) = make_uint2(l0, l1);
}

// ============================ QKV projection (mma.sync bf16) ===============
// 512 thr = 16 warps: wr=wid&3 -> 32 m-rows, wc=wid>>2 -> 16 n-cols.
// Tile M=128 x N=64, K=256 in four 64-k chunks, 2-stage cp.async.
// A = W[m][k] (ldmatrix), B = x[k][n] (ldmatrix.trans). 3-term bf16 split.
__global__ __launch_bounds__(512, 1) void qkv_kernel(
    const float* __restrict__ mask, const float* __restrict__ bq,
    const float* __restrict__ bk, const float* __restrict__ bv)
{
    extern __shared__ char smq[];
    const uint32_t sb = (uint32_t)__cvta_generic_to_shared(smq);

    const int tid = threadIdx.x, lane = tid & 31, wid = tid >> 5;
    const int wr = wid & 3, wc = wid >> 2;
    const int tq = lane >> 2, tr = lane & 3;
    const int n0 = blockIdx.x * 64, m0 = blockIdx.y * 128, b = blockIdx.z;

    auto issue = [&](int ci, int buf) {
        char* st = smq + buf * 49152;
        const int kc = ci * 64;
        #pragma unroll
        for (int it = 0; it < 2; it++) {
            int idx = tid + it * 512;
            int m = idx >> 3, k16 = idx & 7;
            uint32_t d = m * 128 + ((k16 * 16) ^ ((m & 7) << 4));
            size_t s = (size_t)(m0 + m) * 256 + kc + k16 * 8;
            cp16(st + d, g_wh + s);
            cp16(st + 16384 + d, g_wl + s);
        }
        {
            int k = tid >> 3, n16 = tid & 7;
            uint32_t d = k * 128 + ((n16 * 16) ^ ((k & 7) << 4));
            size_t s = ((size_t)(b * NC) + kc + k) * NP + n0 + n16 * 8;
            cp16(st + 32768 + d, g_xh + s);
            cp16(st + 40960 + d, g_xl + s);
        }
        CP_COMMIT;
    };

    float acc[2][2][4];
    #pragma unroll
    for (int mt = 0; mt < 2; mt++)
        #pragma unroll
        for (int nt = 0; nt < 2; nt++)
            #pragma unroll
            for (int d = 0; d < 4; d++) acc[mt][nt][d] = 0.f;

    issue(0, 0);
    for (int ci = 0; ci < 4; ci++) {
        int nxt = (ci + 1 < 4) ? ci + 1 : 3;
        issue(nxt, (ci + 1) & 1);
        CP_WAIT(1);
        __syncthreads();
        const uint32_t wh_b = sb + (ci & 1) * 49152;
        const uint32_t wl_b = wh_b + 16384;
        const uint32_t xh_b = wh_b + 32768;
        const uint32_t xl_b = wh_b + 40960;

        #pragma unroll
        for (int kc = 0; kc < 4; kc++) {
            int krow = kc * 16 + (lane & 7) + ((lane >> 3) & 1) * 8;
            uint32_t nbyte = wc * 32 + ((lane >> 4) << 4);
            uint32_t xa = krow * 128 + (nbyte ^ ((krow & 7) << 4));
            uint32_t bh[4], bl[4];
            ldsm4t(bh, xh_b + xa);
            ldsm4t(bl, xl_b + xa);
            #pragma unroll
            for (int mt = 0; mt < 2; mt++) {
                int ai = wr * 32 + mt * 16 + (lane & 15);
                uint32_t abyte = ai * 128 + ((kc * 32 + (lane >> 4) * 16) ^ ((ai & 7) << 4));
                uint32_t ah[4], al[4];
                ldsm4(ah, wh_b + abyte);
                ldsm4(al, wl_b + abyte);
                mma16816(acc[mt][0], ah, bh);     mma16816(acc[mt][0], ah, bl);     mma16816(acc[mt][0], al, bh);
                mma16816(acc[mt][1], ah, bh + 2); mma16816(acc[mt][1], ah, bl + 2); mma16816(acc[mt][1], al, bh + 2);
            }
        }
        __syncthreads();
    }
    CP_WAIT(0);

    const int sel = m0 >> 8;   // 0:q 1:k 2:v
    float mk[2][2]; int pr_[2][2];
    #pragma unroll
    for (int nt = 0; nt < 2; nt++)
        #pragma unroll
        for (int e = 0; e < 2; e++) {
            int ng = n0 + wc * 16 + nt * 8 + tr * 2 + e;
            mk[nt][e] = mask[(size_t)b * NP + ng];
            pr_[nt][e] = g_pr[(size_t)b * NP + ng];
        }

    #pragma unroll
    for (int mt = 0; mt < 2; mt++)
        #pragma unroll
        for (int half = 0; half < 2; half++) {
            const int o = (m0 & 255) + wr * 32 + mt * 16 + tq + half * 8;
            if (sel == 0) {
                const float bb = bq[o];
                #pragma unroll
                for (int nt = 0; nt < 2; nt++)
                    #pragma unroll
                    for (int e = 0; e < 2; e++)
                        if (mk[nt][e] > 0.5f) {
                            bf16 hh, ll; bfsplit(acc[mt][nt][half * 2 + e] + bb, hh, ll);
                            size_t off = ((size_t)b * NPQ + pr_[nt][e]) * NC + o;
                            g_qh[off] = hh; g_ql[off] = ll;
                        }
            } else if (sel == 1) {
                const float bb = bk[o];
                #pragma unroll
                for (int nt = 0; nt < 2; nt++)
                    #pragma unroll
                    for (int e = 0; e < 2; e++)
                        if (mk[nt][e] < 0.5f) {
                            bf16 hh, ll; bfsplit(acc[mt][nt][half * 2 + e] + bb, hh, ll);
                            size_t off = ((size_t)b * NPQ + pr_[nt][e]) * NC + o;
                            g_kh[off] = hh; g_kl[off] = ll;
                        }
            } else {
                const float bb = bv[o];
                #pragma unroll
                for (int nt = 0; nt < 2; nt++)
                    #pragma unroll
                    for (int e = 0; e < 2; e++)
                        if (mk[nt][e] < 0.5f) {
                            bf16 hh, ll; bfsplit(acc[mt][nt][half * 2 + e] + bb, hh, ll);
                            size_t off = ((size_t)b * NC + o) * NPQ + pr_[nt][e];
                            g_vh[off] = hh; g_vl[off] = ll;
                        }
            }
        }
}

// ============================ pad ==========================================
__global__ __launch_bounds__(256, 1) void pad_kernel(
    const float* __restrict__ bq, const float* __restrict__ bk,
    const float* __restrict__ bv)
{
    const int b = blockIdx.x, sec = blockIdx.y, tid = threadIdx.x;
    const int nf = g_cnt[b * 2], nb = g_cnt[b * 2 + 1];
    if (sec == 0) {
        const int NQ = ((nf + 64) >> 6) << 6;
        const int tot = (NQ - nf) * NC;
        for (int idx = tid; idx < tot; idx += 256) {
            int p = nf + (idx >> 8), c = idx & 255;
            bf16 h(__float2bfloat16(0.f)), l(__float2bfloat16(0.f));
            if (p == nf) bfsplit(bq[c], h, l);
            size_t off = ((size_t)b * NPQ + p) * NC + c;
            g_qh[off] = h; g_ql[off] = l;
        }
    } else if (sec == 1) {
        const int NK = ((nb + 128) >> 7) << 7;
        const int tot = (NK - nb) * NC;
        for (int idx = tid; idx < tot; idx += 256) {
            int p = nb + (idx >> 8), c = idx & 255;
            bf16 h(__float2bfloat16(0.f)), l(__float2bfloat16(0.f));
            if (p == nb) bfsplit(bk[c], h, l);
            size_t off = ((size_t)b * NPQ + p) * NC + c;
            g_kh[off] = h; g_kl[off] = l;
        }
    } else {
        const int NK = ((nb + 128) >> 7) << 7;
        for (int p = nb; p < NK; p++) {
            bf16 h(__float2bfloat16(0.f)), l(__float2bfloat16(0.f));
            if (p == nb) bfsplit(bv[tid], h, l);
            size_t off = ((size_t)b * NC + tid) * NPQ + p;
            g_vh[off] = h; g_vl[off] = l;
        }
    }
}

// ============================ flash attention (mma.sync bf16) ==============
__global__ __launch_bounds__(512, 1) void attn_kernel()
{
    extern __shared__ char smc[];
    char* Pool = smc + 65536;
    char* Psh  = smc + 196608;
    char* Psl  = smc + 212992;
    float* Red = (float*)(smc + 229376);
    float* m_s = Red; float* l_s = Red + 64; float* A_s = Red + 128;
    float* Rmax = Red + 192; float* Rsum = Red + 448;

    const uint32_t sb = (uint32_t)__cvta_generic_to_shared(smc);
    const uint32_t qh_b = sb, ql_b = sb + 32768;
    const uint32_t pool_b = sb + 65536;
    const uint32_t psh_b = sb + 196608, psl_b = sb + 212992;

    const int tid = threadIdx.x, lane = tid & 31, wid = tid >> 5;
    const int wr = wid & 3, wc = wid >> 2;
    const int tq = lane >> 2, tr = lane & 3;
    const int b = blockIdx.y, i0 = blockIdx.x * 64;

    const int nf = g_cnt[b * 2], nb = g_cnt[b * 2 + 1];
    if (i0 >= nf + 1) return;
    const int nkt = (nb + 128) >> 7;
    const float wF = (float)nf;
    const int r0 = 16 * wr + tq, r1 = r0 + 8;

    auto loadK = [&](int ck, int j0, char* buf) {
        #pragma unroll
        for (int it = 0; it < 2; it++) {
            int idx = tid + it * 512;
            int j = idx >> 3, c16 = idx & 7;
            uint32_t d = j * 128 + ((c16 * 16) ^ ((j & 7) << 4));
            size_t s = ((size_t)b * NPQ + j0 + j) * NC + ck * 64 + c16 * 8;
            cp16(buf + d, g_kh + s);
            cp16(buf + 16384 + d, g_kl + s);
        }
        CP_COMMIT;
    };
    auto loadV = [&](int cc, int j0, char* buf) {
        #pragma unroll
        for (int it = 0; it < 2; it++) {
            int idx = tid + it * 512;
            int c = idx >> 4, j16 = idx & 15;
            uint32_t d = c * 256 + ((j16 * 16) ^ ((c & 7) << 4));
            size_t s = ((size_t)b * NC + cc * 64 + c) * NPQ + j0 + j16 * 8;
            cp16(buf + d, g_vh + s);
            cp16(buf + 16384 + d, g_vl + s);
        }
        CP_COMMIT;
    };

    #pragma unroll
    for (int it = 0; it < 4; it++) {
        int idx = tid + it * 512;
        int i = idx >> 5, c16 = idx & 31;
        uint32_t d = i * 512 + ((c16 * 16) ^ ((i & 7) << 4));
        size_t s = ((size_t)b * NPQ + i0 + i) * NC + c16 * 8;
        cp16(smc + d, g_qh + s);
        cp16(smc + 32768 + d, g_ql + s);
    }
    loadK(0, 0, Pool);
    loadK(1, 0, Pool + 32768);

    if (tid < 64) { m_s[tid] = -1e30f; l_s[tid] = 0.f; }

    float sacc[4][4];
    float oa[4][2][4];
    #pragma unroll
    for (int cc = 0; cc < 4; cc++)
        #pragma unroll
        for (int nt = 0; nt < 2; nt++)
            #pragma unroll
            for (int d = 0; d < 4; d++) oa[cc][nt][d] = 0.f;

    const int qtot = nkt * 8;
    for (int q = 0; q < qtot; q++) {
        CP_WAIT(1);
        __syncthreads();
        const int q2 = q + 2;
        if (q2 < qtot) {
            char* buf2 = Pool + (q2 & 3) * 32768;
            int jt2 = q2 >> 3, ph2 = q2 & 7;
            if (ph2 < 4) loadK(ph2, jt2 << 7, buf2);
            else loadV(ph2 - 4, jt2 << 7, buf2);
        } else CP_COMMIT;

        const int ph = q & 7, jt = q >> 3;
        const uint32_t bufb = pool_b + (q & 3) * 32768;

        if (ph < 4) {
            if (ph == 0) {
                #pragma unroll
                for (int nt = 0; nt < 4; nt++)
                    #pragma unroll
                    for (int d = 0; d < 4; d++) sacc[nt][d] = 0.f;
            }
            const int ai = 16 * wr + (lane & 15);
            const int bj = 32 * wc + (lane & 7) + ((lane >> 4) << 3);
            const int bj1 = bj + 16;
            #pragma unroll
            for (int kc = 0; kc < 4; kc++) {
                uint32_t abyte = ai * 512 +
                    ((((ph * 64 + kc * 16) * 2) + (lane >> 4) * 16) ^ ((ai & 7) << 4));
                uint32_t ah[4], al[4];
                ldsm4(ah, qh_b + abyte);
                ldsm4(al, ql_b + abyte);
                uint32_t bbyte = kc * 32 + ((lane >> 3) & 1) * 16;
                uint32_t ka0 = bufb + bj * 128 + (bbyte ^ ((bj & 7) << 4));
                uint32_t ka1 = bufb + bj1 * 128 + (bbyte ^ ((bj1 & 7) << 4));
                uint32_t bh0[4], bl0[4], bh1[4], bl1[4];
                ldsm4(bh0, ka0); ldsm4(bl0, ka0 + 16384);
                ldsm4(bh1, ka1); ldsm4(bl1, ka1 + 16384);
                mma16816(sacc[0], ah, bh0);     mma16816(sacc[0], ah, bl0);     mma16816(sacc[0], al, bh0);
                mma16816(sacc[1], ah, bh0 + 2); mma16816(sacc[1], ah, bl0 + 2); mma16816(sacc[1], al, bh0 + 2);
                mma16816(sacc[2], ah, bh1);     mma16816(sacc[2], ah, bl1);     mma16816(sacc[2], al, bh1);
                mma16816(sacc[3], ah, bh1 + 2); mma16816(sacc[3], ah, bl1 + 2); mma16816(sacc[3], al, bh1 + 2);
            }
        } else {
            if (ph == 4) {
                const int j0 = jt << 7;
                float mx0 = -1e30f, mx1 = -1e30f;
                #pragma unroll
                for (int nt = 0; nt < 4; nt++)
                    #pragma unroll
                    for (int e = 0; e < 2; e++) {
                        int jg = j0 + 32 * wc + 8 * nt + 2 * tr + e;
                        if (jg > nb) { sacc[nt][e] = -1e30f; sacc[nt][2 + e] = -1e30f; }
                        mx0 = fmaxf(mx0, sacc[nt][e]);
                        mx1 = fmaxf(mx1, sacc[nt][2 + e]);
                    }
                #pragma unroll
                for (int off = 1; off < 4; off <<= 1) {
                    mx0 = fmaxf(mx0, __shfl_xor_sync(0xffffffffu, mx0, off));
                    mx1 = fmaxf(mx1, __shfl_xor_sync(0xffffffffu, mx1, off));
                }
                if (tr == 0) { Rmax[wc * 64 + r0] = mx0; Rmax[wc * 64 + r1] = mx1; }
                __syncthreads();
                if (tid < 64) {
                    float mt = fmaxf(fmaxf(Rmax[tid], Rmax[64 + tid]),
                                     fmaxf(Rmax[128 + tid], Rmax[192 + tid]));
                    float mo = m_s[tid];
                    float mn = fmaxf(mo, mt);
                    m_s[tid] = mn;
                    A_s[tid] = __expf(mo - mn);
                }
                __syncthreads();
                const float mn0 = m_s[r0], mn1 = m_s[r1];
                const float a0 = A_s[r0], a1 = A_s[r1];
                #pragma unroll
                for (int cc = 0; cc < 4; cc++)
                    #pragma unroll
                    for (int nt = 0; nt < 2; nt++) {
                        oa[cc][nt][0] *= a0; oa[cc][nt][1] *= a0;
                        oa[cc][nt][2] *= a1; oa[cc][nt][3] *= a1;
                    }
                float sm0 = 0.f, sm1 = 0.f;
                #pragma unroll
                for (int nt = 0; nt < 4; nt++) {
                    int jg0 = j0 + 32 * wc + 8 * nt + 2 * tr;
                    float w0 = (jg0 == nb) ? wF : 1.f;
                    float w1 = (jg0 + 1 == nb) ? wF : 1.f;
                    float p00 = __expf(sacc[nt][0] - mn0) * w0;
                    float p01 = __expf(sacc[nt][1] - mn0) * w1;
                    float p10 = __expf(sacc[nt][2] - mn1) * w0;
                    float p11 = __expf(sacc[nt][3] - mn1) * w1;
                    sm0 += p00 + p01; sm1 += p10 + p11;
                    uint32_t h, l;
                    int colb = (32 * wc + 8 * nt + 2 * tr) * 2;
                    split2(p00, p01, h, l);
                    *(uint32_t*)(Psh + r0 * 256 + (colb ^ ((r0 & 7) << 4))) = h;
                    *(uint32_t*)(Psl + r0 * 256 + (colb ^ ((r0 & 7) << 4))) = l;
                    split2(p10, p11, h, l);
                    *(uint32_t*)(Psh + r1 * 256 + (colb ^ ((r1 & 7) << 4))) = h;
                    *(uint32_t*)(Psl + r1 * 256 + (colb ^ ((r1 & 7) << 4))) = l;
                }
                #pragma unroll
                for (int off = 1; off < 4; off <<= 1) {
                    sm0 += __shfl_xor_sync(0xffffffffu, sm0, off);
                    sm1 += __shfl_xor_sync(0xffffffffu, sm1, off);
                }
                if (tr == 0) { Rsum[wc * 64 + r0] = sm0; Rsum[wc * 64 + r1] = sm1; }
                __syncthreads();
                if (tid < 64)
                    l_s[tid] = l_s[tid] * A_s[tid] +
                        Rsum[tid] + Rsum[64 + tid] + Rsum[128 + tid] + Rsum[192 + tid];
            }
            const int cc = ph - 4;
            const int ai = 16 * wr + (lane & 15);
            const int cn = 16 * wc + (lane & 7) + ((lane >> 4) << 3);
            #pragma unroll
            for (int jc = 0; jc < 8; jc++) {
                uint32_t abyte = ai * 256 + ((jc * 32 + (lane >> 4) * 16) ^ ((ai & 7) << 4));
                uint32_t ph4[4], pl4[4];
                ldsm4(ph4, psh_b + abyte);
                ldsm4(pl4, psl_b + abyte);
                uint32_t bbyte = jc * 32 + ((lane >> 3) & 1) * 16;
                uint32_t va = bufb + cn * 256 + (bbyte ^ ((cn & 7) << 4));
                uint32_t vh4[4], vl4[4];
                ldsm4(vh4, va); ldsm4(vl4, va + 16384);
                mma16816(oa[cc][0], ph4, vh4);     mma16816(oa[cc][0], ph4, vl4);     mma16816(oa[cc][0], pl4, vh4);
                mma16816(oa[cc][1], ph4, vh4 + 2); mma16816(oa[cc][1], ph4, vl4 + 2); mma16816(oa[cc][1], pl4, vh4 + 2);
            }
        }
    }
    CP_WAIT(0);
    __syncthreads();

    const float inv0 = 1.f / l_s[r0], inv1 = 1.f / l_s[r1];
    #pragma unroll
    for (int cc = 0; cc < 4; cc++)
        #pragma unroll
        for (int nt = 0; nt < 2; nt++) {
            int c = 64 * cc + 16 * wc + 8 * nt + 2 * tr;
            float* d0 = &g_go[(size_t)(b * NC + c) * NPQ + i0];
            float* d1 = &g_go[(size_t)(b * NC + c + 1) * NPQ + i0];
            d0[r0] = oa[cc][nt][0] * inv0;
            d1[r0] = oa[cc][nt][1] * inv0;
            d0[r1] = oa[cc][nt][2] * inv1;
            d1[r1] = oa[cc][nt][3] * inv1;
        }
}

// ============================ output projection ============================
__global__ __launch_bounds__(256, 2) void proj_kernel(
    const float* __restrict__ Wo, const float* __restrict__ bo)
{
    __shared__ float Ws[32][132];
    __shared__ float Xs[32][64];
    const int tid = threadIdx.x;
    const int tx = tid & 15, ty = tid >> 4;
    const int n0 = blockIdx.x * 64, m0 = blockIdx.y * 128, b = blockIdx.z;
    const int nfq = g_cnt[b * 2] + 1;
    if (n0 >= nfq) return;

    ull acc[4][4];
    #pragma unroll
    for (int mp = 0; mp < 4; mp++)
        #pragma unroll
        for (int jj = 0; jj < 4; jj++) acc[mp][jj] = 0ull;

    for (int kc = 0; kc < NC; kc += 32) {
        #pragma unroll
        for (int it = 0; it < 16; it++) {
            int idx = tid + it * 256;
            int m = idx >> 5, kk = idx & 31;
            Ws[kk][m] = Wo[(m0 + m) * 256 + kc + kk];
        }
        #pragma unroll
        for (int it = 0; it < 2; it++) {
            int idx = tid + it * 256;
            int k = idx >> 4, j4 = idx & 15;
            *reinterpret_cast<float4*>(&Xs[k][j4 * 4]) =
                *reinterpret_cast<const float4*>(&g_go[(size_t)(b * NC + kc + k) * NPQ + n0 + j4 * 4]);
        }
        __syncthreads();
        #pragma unroll 8
        for (int k = 0; k < 32; k++) {
            ulonglong2 w01 = *reinterpret_cast<const ulonglong2*>(&Ws[k][ty * 8]);
            ulonglong2 w23 = *reinterpret_cast<const ulonglong2*>(&Ws[k][ty * 8 + 4]);
            float4 xv = *reinterpret_cast<const float4*>(&Xs[k][tx * 4]);
            ull wp[4] = { w01.x, w01.y, w23.x, w23.y };
            ull xd[4] = { pack2(xv.x, xv.x), pack2(xv.y, xv.y),
                          pack2(xv.z, xv.z), pack2(xv.w, xv.w) };
            #pragma unroll
            for (int mp = 0; mp < 4; mp++)
                #pragma unroll
                for (int jj = 0; jj < 4; jj++)
                    acc[mp][jj] = fma2(wp[mp], xd[jj], acc[mp][jj]);
        }
        __syncthreads();
    }

    #pragma unroll
    for (int mp = 0; mp < 4; mp++) {
        float2 u[4];
        #pragma unroll
        for (int jj = 0; jj < 4; jj++) u[jj] = unpack2(acc[mp][jj]);
        #pragma unroll
        for (int h = 0; h < 2; h++) {
            int o = m0 + ty * 8 + mp * 2 + h;
            float bb = bo[o];
            float4 r;
            r.x = (h ? u[0].y : u[0].x) + bb;
            r.y = (h ? u[1].y : u[1].x) + bb;
            r.z = (h ? u[2].y : u[2].x) + bb;
            r.w = (h ? u[3].y : u[3].x) + bb;
            *reinterpret_cast<float4*>(&g_p[(size_t)(b * NC + o) * NPQ + n0 + tx * 4]) = r;
        }
    }
}

// ============================ scatter ======================================
__global__ __launch_bounds__(256, 1) void scatter_kernel(
    const float* __restrict__ x, const float* __restrict__ gamma,
    float* __restrict__ out)
{
    const int b = blockIdx.y;
    const int n = blockIdx.x * 256 + threadIdx.x;
    const int ci = g_cidx[(size_t)b * NP + n];
    const float g0 = gamma[0];
    const float* px = x + (size_t)b * NC * NP + n;
    const float* pp = g_p + (size_t)b * NC * NPQ + ci;
    float* po = out + (size_t)b * NC * NP + n;
    #pragma unroll 4
    for (int c = 0; c < NC; c++)
        po[(size_t)c * NP] = pp[(size_t)c * NPQ] + g0 * px[(size_t)c * NP];
}

extern "C" void kernel_launch(void* const* d_in, const int* in_sizes, int n_in,
                              void* d_out, int out_size)
{
    const float* x     = (const float*)d_in[0];
    const float* mask  = (const float*)d_in[1];
    const float* Wq    = (const float*)d_in[2];
    const float* bq    = (const float*)d_in[3];
    const float* Wk    = (const float*)d_in[4];
    const float* bk    = (const float*)d_in[5];
    const float* Wv    = (const float*)d_in[6];
    const float* bv    = (const float*)d_in[7];
    const float* Wo    = (const float*)d_in[8];
    const float* bo    = (const float*)d_in[9];
    const float* gamma = (const float*)d_in[10];
    float* out = (float*)d_out;

    compact_kernel<<<NB, 256>>>(mask);
    wsplit_kernel<<<768, 256>>>(Wq, Wk, Wv);
    xsplit_kernel<<<(NB * NC * NP) / 1024, 256>>>(x);

    cudaFuncSetAttribute(qkv_kernel, cudaFuncAttributeMaxDynamicSharedMemorySize, 98304);
    qkv_kernel<<<dim3(64, 6, NB), 512, 98304>>>(mask, bq, bk, bv);

    pad_kernel<<<dim3(NB, 3), 256>>>(bq, bk, bv);

    const size_t smemB = 232192;
    cudaFuncSetAttribute(attn_kernel, cudaFuncAttributeMaxDynamicSharedMemorySize, (int)smemB);
    attn_kernel<<<dim3(65, NB), 512, smemB>>>();

    proj_kernel<<<dim3(65, 2, NB), 256>>>(Wo, bo);
    scatter_kernel<<<dim3(16, NB), 256>>>(x, gamma, out);
}

// round 13
// speedup vs baseline: 1.5987x; 1.0251x over previous
#include <cuda_runtime.h>
#include <cuda_bf16.h>
#include <cstdint>

#define NB 8
#define NC 256
#define NP 4096
#define NPQ 4224

typedef unsigned long long ull;
typedef __nv_bfloat16 bf16;

__device__ bf16  g_qh[NB * NPQ * NC];   // q hi [b][p][c]
__device__ bf16  g_ql[NB * NPQ * NC];
__device__ bf16  g_kh[NB * NPQ * NC];   // k hi [b][p][c]
__device__ bf16  g_kl[NB * NPQ * NC];
__device__ bf16  g_vh[NB * NC * NPQ];   // v hi [b][c][p]
__device__ bf16  g_vl[NB * NC * NPQ];
__device__ bf16  g_wh[768 * 256];       // stacked Wq/Wk/Wv hi [o][c]
__device__ bf16  g_wl[768 * 256];
__device__ bf16  g_woh[256 * 256];      // Wo hi [o][c]
__device__ bf16  g_wol[256 * 256];
__device__ bf16  g_xh[NB * NC * NP];    // x hi [b][c][n]
__device__ bf16  g_xl[NB * NC * NP];
__device__ bf16  g_goh[NB * NC * NPQ];  // attn out hi [b][c][p]
__device__ bf16  g_gol[NB * NC * NPQ];
__device__ float g_p [NB * NC * NPQ];
__device__ int   g_pr[NB * NP];
__device__ int   g_cidx[NB * NP];
__device__ int   g_cnt[NB * 2];

__device__ __forceinline__ void cp16(void* dst, const void* src) {
    unsigned s = (unsigned)__cvta_generic_to_shared(dst);
    asm volatile("cp.async.cg.shared.global [%0], [%1], 16;" :: "r"(s), "l"(src));
}
#define CP_COMMIT asm volatile("cp.async.commit_group;" ::: "memory")
#define CP_WAIT(n) asm volatile("cp.async.wait_group %0;" :: "n"(n) : "memory")

__device__ __forceinline__ void bfsplit(float x, bf16& h, bf16& l) {
    h = __float2bfloat16(x);
    l = __float2bfloat16(x - __bfloat162float(h));
}
__device__ __forceinline__ void split2(float a, float b, uint32_t& h, uint32_t& l) {
    bf16 ah, al, bh, bl;
    bfsplit(a, ah, al); bfsplit(b, bh, bl);
    h = (uint32_t)__bfloat16_as_ushort(ah) | ((uint32_t)__bfloat16_as_ushort(bh) << 16);
    l = (uint32_t)__bfloat16_as_ushort(al) | ((uint32_t)__bfloat16_as_ushort(bl) << 16);
}
__device__ __forceinline__ void ldsm4(uint32_t* r, uint32_t a) {
    asm volatile("ldmatrix.sync.aligned.m8n8.x4.shared.b16 {%0,%1,%2,%3}, [%4];"
        : "=r"(r[0]), "=r"(r[1]), "=r"(r[2]), "=r"(r[3]) : "r"(a));
}
__device__ __forceinline__ void ldsm4t(uint32_t* r, uint32_t a) {
    asm volatile("ldmatrix.sync.aligned.m8n8.x4.trans.shared.b16 {%0,%1,%2,%3}, [%4];"
        : "=r"(r[0]), "=r"(r[1]), "=r"(r[2]), "=r"(r[3]) : "r"(a));
}
__device__ __forceinline__ void mma16816(float* d, const uint32_t* a, const uint32_t* b) {
    asm volatile("mma.sync.aligned.m16n8k16.row.col.f32.bf16.bf16.f32 "
        "{%0,%1,%2,%3},{%4,%5,%6,%7},{%8,%9},{%0,%1,%2,%3};"
        : "+f"(d[0]), "+f"(d[1]), "+f"(d[2]), "+f"(d[3])
        : "r"(a[0]), "r"(a[1]), "r"(a[2]), "r"(a[3]), "r"(b[0]), "r"(b[1]));
}

// ============================ compaction ===================================
__global__ __launch_bounds__(256, 1) void compact_kernel(const float* __restrict__ mask)
{
    const int b = blockIdx.x, tid = threadIdx.x;
    const int lane = tid & 31, wid = tid >> 5;
    __shared__ int wsum[8];
    __shared__ int s_nf;
    bool f[16]; int c = 0;
    const float* mb = mask + (size_t)b * NP;
    #pragma unroll
    for (int i = 0; i < 16; i++) { f[i] = mb[tid * 16 + i] > 0.5f; c += f[i]; }
    int v = c;
    #pragma unroll
    for (int off = 1; off < 32; off <<= 1) {
        int u = __shfl_up_sync(0xffffffffu, v, off);
        if (lane >= off) v += u;
    }
    if (lane == 31) wsum[wid] = v;
    __syncthreads();
    if (tid < 8) {
        int wv = wsum[tid];
        #pragma unroll
        for (int off = 1; off < 8; off <<= 1) {
            int u = __shfl_up_sync(0xffu, wv, off);
            if (tid >= off) wv += u;
        }
        wsum[tid] = wv;
        if (tid == 7) s_nf = wv;
    }
    __syncthreads();
    const int nf = s_nf;
    int excl = v - c + (wid ? wsum[wid - 1] : 0);
    int fo = excl, bo = tid * 16 - excl;
    int* pr = g_pr + (size_t)b * NP;
    int* cidx = g_cidx + (size_t)b * NP;
    #pragma unroll
    for (int i = 0; i < 16; i++) {
        int n = tid * 16 + i;
        if (f[i]) { pr[n] = fo; cidx[n] = fo; fo++; }
        else      { pr[n] = bo; cidx[n] = nf; bo++; }
    }
    if (tid == 0) { g_cnt[b * 2] = nf; g_cnt[b * 2 + 1] = NP - nf; }
}

// ============================ W / x bf16 split prep ========================
__global__ __launch_bounds__(256, 4) void wsplit_kernel(
    const float* __restrict__ Wq, const float* __restrict__ Wk,
    const float* __restrict__ Wv, const float* __restrict__ Wo)
{
    const int row = blockIdx.x;        // 0..1023
    const int c = threadIdx.x;
    if (row < 768) {
        const float* W = (row < 256) ? Wq : ((row < 512) ? Wk : Wv);
        bf16 h, l; bfsplit(W[(row & 255) * 256 + c], h, l);
        g_wh[row * 256 + c] = h;
        g_wl[row * 256 + c] = l;
    } else {
        bf16 h, l; bfsplit(Wo[(row & 255) * 256 + c], h, l);
        g_woh[(row & 255) * 256 + c] = h;
        g_wol[(row & 255) * 256 + c] = l;
    }
}

__global__ __launch_bounds__(256, 4) void xsplit_kernel(const float* __restrict__ x)
{
    const size_t i = ((size_t)blockIdx.x * 256 + threadIdx.x) * 4;
    float4 v = *reinterpret_cast<const float4*>(x + i);
    uint32_t h0, l0, h1, l1;
    split2(v.x, v.y, h0, l0);
    split2(v.z, v.w, h1, l1);
    *reinterpret_cast<uint2*>(g_xh + i) = make_uint2(h0, h1);
    *reinterpret_cast<uint2*>(g_xl + i) = make_uint2(l0, l1);
}

// ============================ QKV projection (mma.sync bf16) ===============
__global__ __launch_bounds__(512, 1) void qkv_kernel(
    const float* __restrict__ mask, const float* __restrict__ bq,
    const float* __restrict__ bk, const float* __restrict__ bv)
{
    extern __shared__ char smq[];
    const uint32_t sb = (uint32_t)__cvta_generic_to_shared(smq);

    const int tid = threadIdx.x, lane = tid & 31, wid = tid >> 5;
    const int wr = wid & 3, wc = wid >> 2;
    const int tq = lane >> 2, tr = lane & 3;
    const int n0 = blockIdx.x * 64, m0 = blockIdx.y * 128, b = blockIdx.z;

    auto issue = [&](int ci, int buf) {
        char* st = smq + buf * 49152;
        const int kc = ci * 64;
        #pragma unroll
        for (int it = 0; it < 2; it++) {
            int idx = tid + it * 512;
            int m = idx >> 3, k16 = idx & 7;
            uint32_t d = m * 128 + ((k16 * 16) ^ ((m & 7) << 4));
            size_t s = (size_t)(m0 + m) * 256 + kc + k16 * 8;
            cp16(st + d, g_wh + s);
            cp16(st + 16384 + d, g_wl + s);
        }
        {
            int k = tid >> 3, n16 = tid & 7;
            uint32_t d = k * 128 + ((n16 * 16) ^ ((k & 7) << 4));
            size_t s = ((size_t)(b * NC) + kc + k) * NP + n0 + n16 * 8;
            cp16(st + 32768 + d, g_xh + s);
            cp16(st + 40960 + d, g_xl + s);
        }
        CP_COMMIT;
    };

    float acc[2][2][4];
    #pragma unroll
    for (int mt = 0; mt < 2; mt++)
        #pragma unroll
        for (int nt = 0; nt < 2; nt++)
            #pragma unroll
            for (int d = 0; d < 4; d++) acc[mt][nt][d] = 0.f;

    issue(0, 0);
    for (int ci = 0; ci < 4; ci++) {
        int nxt = (ci + 1 < 4) ? ci + 1 : 3;
        issue(nxt, (ci + 1) & 1);
        CP_WAIT(1);
        __syncthreads();
        const uint32_t wh_b = sb + (ci & 1) * 49152;
        const uint32_t wl_b = wh_b + 16384;
        const uint32_t xh_b = wh_b + 32768;
        const uint32_t xl_b = wh_b + 40960;

        #pragma unroll
        for (int kc = 0; kc < 4; kc++) {
            int krow = kc * 16 + (lane & 7) + ((lane >> 3) & 1) * 8;
            uint32_t nbyte = wc * 32 + ((lane >> 4) << 4);
            uint32_t xa = krow * 128 + (nbyte ^ ((krow & 7) << 4));
            uint32_t bh[4], bl[4];
            ldsm4t(bh, xh_b + xa);
            ldsm4t(bl, xl_b + xa);
            #pragma unroll
            for (int mt = 0; mt < 2; mt++) {
                int ai = wr * 32 + mt * 16 + (lane & 15);
                uint32_t abyte = ai * 128 + ((kc * 32 + (lane >> 4) * 16) ^ ((ai & 7) << 4));
                uint32_t ah[4], al[4];
                ldsm4(ah, wh_b + abyte);
                ldsm4(al, wl_b + abyte);
                mma16816(acc[mt][0], ah, bh);     mma16816(acc[mt][0], ah, bl);     mma16816(acc[mt][0], al, bh);
                mma16816(acc[mt][1], ah, bh + 2); mma16816(acc[mt][1], ah, bl + 2); mma16816(acc[mt][1], al, bh + 2);
            }
        }
        __syncthreads();
    }
    CP_WAIT(0);

    const int sel = m0 >> 8;
    float mk[2][2]; int pr_[2][2];
    #pragma unroll
    for (int nt = 0; nt < 2; nt++)
        #pragma unroll
        for (int e = 0; e < 2; e++) {
            int ng = n0 + wc * 16 + nt * 8 + tr * 2 + e;
            mk[nt][e] = mask[(size_t)b * NP + ng];
            pr_[nt][e] = g_pr[(size_t)b * NP + ng];
        }

    #pragma unroll
    for (int mt = 0; mt < 2; mt++)
        #pragma unroll
        for (int half = 0; half < 2; half++) {
            const int o = (m0 & 255) + wr * 32 + mt * 16 + tq + half * 8;
            if (sel == 0) {
                const float bb = bq[o];
                #pragma unroll
                for (int nt = 0; nt < 2; nt++)
                    #pragma unroll
                    for (int e = 0; e < 2; e++)
                        if (mk[nt][e] > 0.5f) {
                            bf16 hh, ll; bfsplit(acc[mt][nt][half * 2 + e] + bb, hh, ll);
                            size_t off = ((size_t)b * NPQ + pr_[nt][e]) * NC + o;
                            g_qh[off] = hh; g_ql[off] = ll;
                        }
            } else if (sel == 1) {
                const float bb = bk[o];
                #pragma unroll
                for (int nt = 0; nt < 2; nt++)
                    #pragma unroll
                    for (int e = 0; e < 2; e++)
                        if (mk[nt][e] < 0.5f) {
                            bf16 hh, ll; bfsplit(acc[mt][nt][half * 2 + e] + bb, hh, ll);
                            size_t off = ((size_t)b * NPQ + pr_[nt][e]) * NC + o;
                            g_kh[off] = hh; g_kl[off] = ll;
                        }
            } else {
                const float bb = bv[o];
                #pragma unroll
                for (int nt = 0; nt < 2; nt++)
                    #pragma unroll
                    for (int e = 0; e < 2; e++)
                        if (mk[nt][e] < 0.5f) {
                            bf16 hh, ll; bfsplit(acc[mt][nt][half * 2 + e] + bb, hh, ll);
                            size_t off = ((size_t)b * NC + o) * NPQ + pr_[nt][e];
                            g_vh[off] = hh; g_vl[off] = ll;
                        }
            }
        }
}

// ============================ pad ==========================================
__global__ __launch_bounds__(256, 1) void pad_kernel(
    const float* __restrict__ bq, const float* __restrict__ bk,
    const float* __restrict__ bv)
{
    const int b = blockIdx.x, sec = blockIdx.y, tid = threadIdx.x;
    const int nf = g_cnt[b * 2], nb = g_cnt[b * 2 + 1];
    if (sec == 0) {
        const int NQ = ((nf + 64) >> 6) << 6;
        const int tot = (NQ - nf) * NC;
        for (int idx = tid; idx < tot; idx += 256) {
            int p = nf + (idx >> 8), c = idx & 255;
            bf16 h(__float2bfloat16(0.f)), l(__float2bfloat16(0.f));
            if (p == nf) bfsplit(bq[c], h, l);
            size_t off = ((size_t)b * NPQ + p) * NC + c;
            g_qh[off] = h; g_ql[off] = l;
        }
    } else if (sec == 1) {
        const int NK = ((nb + 128) >> 7) << 7;
        const int tot = (NK - nb) * NC;
        for (int idx = tid; idx < tot; idx += 256) {
            int p = nb + (idx >> 8), c = idx & 255;
            bf16 h(__float2bfloat16(0.f)), l(__float2bfloat16(0.f));
            if (p == nb) bfsplit(bk[c], h, l);
            size_t off = ((size_t)b * NPQ + p) * NC + c;
            g_kh[off] = h; g_kl[off] = l;
        }
    } else {
        const int NK = ((nb + 128) >> 7) << 7;
        for (int p = nb; p < NK; p++) {
            bf16 h(__float2bfloat16(0.f)), l(__float2bfloat16(0.f));
            if (p == nb) bfsplit(bv[tid], h, l);
            size_t off = ((size_t)b * NC + tid) * NPQ + p;
            g_vh[off] = h; g_vl[off] = l;
        }
    }
}

// ============================ flash attention (mma.sync bf16) ==============
__global__ __launch_bounds__(512, 1) void attn_kernel()
{
    extern __shared__ char smc[];
    char* Pool = smc + 65536;
    char* Psh  = smc + 196608;
    char* Psl  = smc + 212992;
    float* Red = (float*)(smc + 229376);
    float* m_s = Red; float* l_s = Red + 64; float* A_s = Red + 128;
    float* Rmax = Red + 192; float* Rsum = Red + 448;

    const uint32_t sb = (uint32_t)__cvta_generic_to_shared(smc);
    const uint32_t qh_b = sb, ql_b = sb + 32768;
    const uint32_t pool_b = sb + 65536;
    const uint32_t psh_b = sb + 196608, psl_b = sb + 212992;

    const int tid = threadIdx.x, lane = tid & 31, wid = tid >> 5;
    const int wr = wid & 3, wc = wid >> 2;
    const int tq = lane >> 2, tr = lane & 3;
    const int b = blockIdx.y, i0 = blockIdx.x * 64;

    const int nf = g_cnt[b * 2], nb = g_cnt[b * 2 + 1];
    if (i0 >= nf + 1) return;
    const int nkt = (nb + 128) >> 7;
    const float wF = (float)nf;
    const int r0 = 16 * wr + tq, r1 = r0 + 8;

    auto loadK = [&](int ck, int j0, char* buf) {
        #pragma unroll
        for (int it = 0; it < 2; it++) {
            int idx = tid + it * 512;
            int j = idx >> 3, c16 = idx & 7;
            uint32_t d = j * 128 + ((c16 * 16) ^ ((j & 7) << 4));
            size_t s = ((size_t)b * NPQ + j0 + j) * NC + ck * 64 + c16 * 8;
            cp16(buf + d, g_kh + s);
            cp16(buf + 16384 + d, g_kl + s);
        }
        CP_COMMIT;
    };
    auto loadV = [&](int cc, int j0, char* buf) {
        #pragma unroll
        for (int it = 0; it < 2; it++) {
            int idx = tid + it * 512;
            int c = idx >> 4, j16 = idx & 15;
            uint32_t d = c * 256 + ((j16 * 16) ^ ((c & 7) << 4));
            size_t s = ((size_t)b * NC + cc * 64 + c) * NPQ + j0 + j16 * 8;
            cp16(buf + d, g_vh + s);
            cp16(buf + 16384 + d, g_vl + s);
        }
        CP_COMMIT;
    };

    #pragma unroll
    for (int it = 0; it < 4; it++) {
        int idx = tid + it * 512;
        int i = idx >> 5, c16 = idx & 31;
        uint32_t d = i * 512 + ((c16 * 16) ^ ((i & 7) << 4));
        size_t s = ((size_t)b * NPQ + i0 + i) * NC + c16 * 8;
        cp16(smc + d, g_qh + s);
        cp16(smc + 32768 + d, g_ql + s);
    }
    loadK(0, 0, Pool);
    loadK(1, 0, Pool + 32768);

    if (tid < 64) { m_s[tid] = -1e30f; l_s[tid] = 0.f; }

    float sacc[4][4];
    float oa[4][2][4];
    #pragma unroll
    for (int cc = 0; cc < 4; cc++)
        #pragma unroll
        for (int nt = 0; nt < 2; nt++)
            #pragma unroll
            for (int d = 0; d < 4; d++) oa[cc][nt][d] = 0.f;

    const int qtot = nkt * 8;
    for (int q = 0; q < qtot; q++) {
        CP_WAIT(1);
        __syncthreads();
        const int q2 = q + 2;
        if (q2 < qtot) {
            char* buf2 = Pool + (q2 & 3) * 32768;
            int jt2 = q2 >> 3, ph2 = q2 & 7;
            if (ph2 < 4) loadK(ph2, jt2 << 7, buf2);
            else loadV(ph2 - 4, jt2 << 7, buf2);
        } else CP_COMMIT;

        const int ph = q & 7, jt = q >> 3;
        const uint32_t bufb = pool_b + (q & 3) * 32768;

        if (ph < 4) {
            if (ph == 0) {
                #pragma unroll
                for (int nt = 0; nt < 4; nt++)
                    #pragma unroll
                    for (int d = 0; d < 4; d++) sacc[nt][d] = 0.f;
            }
            const int ai = 16 * wr + (lane & 15);
            const int bj = 32 * wc + (lane & 7) + ((lane >> 4) << 3);
            const int bj1 = bj + 16;
            #pragma unroll
            for (int kc = 0; kc < 4; kc++) {
                uint32_t abyte = ai * 512 +
                    ((((ph * 64 + kc * 16) * 2) + (lane >> 4) * 16) ^ ((ai & 7) << 4));
                uint32_t ah[4], al[4];
                ldsm4(ah, qh_b + abyte);
                ldsm4(al, ql_b + abyte);
                uint32_t bbyte = kc * 32 + ((lane >> 3) & 1) * 16;
                uint32_t ka0 = bufb + bj * 128 + (bbyte ^ ((bj & 7) << 4));
                uint32_t ka1 = bufb + bj1 * 128 + (bbyte ^ ((bj1 & 7) << 4));
                uint32_t bh0[4], bl0[4], bh1[4], bl1[4];
                ldsm4(bh0, ka0); ldsm4(bl0, ka0 + 16384);
                ldsm4(bh1, ka1); ldsm4(bl1, ka1 + 16384);
                mma16816(sacc[0], ah, bh0);     mma16816(sacc[0], ah, bl0);     mma16816(sacc[0], al, bh0);
                mma16816(sacc[1], ah, bh0 + 2); mma16816(sacc[1], ah, bl0 + 2); mma16816(sacc[1], al, bh0 + 2);
                mma16816(sacc[2], ah, bh1);     mma16816(sacc[2], ah, bl1);     mma16816(sacc[2], al, bh1);
                mma16816(sacc[3], ah, bh1 + 2); mma16816(sacc[3], ah, bl1 + 2); mma16816(sacc[3], al, bh1 + 2);
            }
        } else {
            if (ph == 4) {
                const int j0 = jt << 7;
                float mx0 = -1e30f, mx1 = -1e30f;
                #pragma unroll
                for (int nt = 0; nt < 4; nt++)
                    #pragma unroll
                    for (int e = 0; e < 2; e++) {
                        int jg = j0 + 32 * wc + 8 * nt + 2 * tr + e;
                        if (jg > nb) { sacc[nt][e] = -1e30f; sacc[nt][2 + e] = -1e30f; }
                        mx0 = fmaxf(mx0, sacc[nt][e]);
                        mx1 = fmaxf(mx1, sacc[nt][2 + e]);
                    }
                #pragma unroll
                for (int off = 1; off < 4; off <<= 1) {
                    mx0 = fmaxf(mx0, __shfl_xor_sync(0xffffffffu, mx0, off));
                    mx1 = fmaxf(mx1, __shfl_xor_sync(0xffffffffu, mx1, off));
                }
                if (tr == 0) { Rmax[wc * 64 + r0] = mx0; Rmax[wc * 64 + r1] = mx1; }
                __syncthreads();
                if (tid < 64) {
                    float mt = fmaxf(fmaxf(Rmax[tid], Rmax[64 + tid]),
                                     fmaxf(Rmax[128 + tid], Rmax[192 + tid]));
                    float mo = m_s[tid];
                    float mn = fmaxf(mo, mt);
                    m_s[tid] = mn;
                    A_s[tid] = __expf(mo - mn);
                }
                __syncthreads();
                const float mn0 = m_s[r0], mn1 = m_s[r1];
                const float a0 = A_s[r0], a1 = A_s[r1];
                #pragma unroll
                for (int cc = 0; cc < 4; cc++)
                    #pragma unroll
                    for (int nt = 0; nt < 2; nt++) {
                        oa[cc][nt][0] *= a0; oa[cc][nt][1] *= a0;
                        oa[cc][nt][2] *= a1; oa[cc][nt][3] *= a1;
                    }
                float sm0 = 0.f, sm1 = 0.f;
                #pragma unroll
                for (int nt = 0; nt < 4; nt++) {
                    int jg0 = j0 + 32 * wc + 8 * nt + 2 * tr;
                    float w0 = (jg0 == nb) ? wF : 1.f;
                    float w1 = (jg0 + 1 == nb) ? wF : 1.f;
                    float p00 = __expf(sacc[nt][0] - mn0) * w0;
                    float p01 = __expf(sacc[nt][1] - mn0) * w1;
                    float p10 = __expf(sacc[nt][2] - mn1) * w0;
                    float p11 = __expf(sacc[nt][3] - mn1) * w1;
                    sm0 += p00 + p01; sm1 += p10 + p11;
                    uint32_t h, l;
                    int colb = (32 * wc + 8 * nt + 2 * tr) * 2;
                    split2(p00, p01, h, l);
                    *(uint32_t*)(Psh + r0 * 256 + (colb ^ ((r0 & 7) << 4))) = h;
                    *(uint32_t*)(Psl + r0 * 256 + (colb ^ ((r0 & 7) << 4))) = l;
                    split2(p10, p11, h, l);
                    *(uint32_t*)(Psh + r1 * 256 + (colb ^ ((r1 & 7) << 4))) = h;
                    *(uint32_t*)(Psl + r1 * 256 + (colb ^ ((r1 & 7) << 4))) = l;
                }
                #pragma unroll
                for (int off = 1; off < 4; off <<= 1) {
                    sm0 += __shfl_xor_sync(0xffffffffu, sm0, off);
                    sm1 += __shfl_xor_sync(0xffffffffu, sm1, off);
                }
                if (tr == 0) { Rsum[wc * 64 + r0] = sm0; Rsum[wc * 64 + r1] = sm1; }
                __syncthreads();
                if (tid < 64)
                    l_s[tid] = l_s[tid] * A_s[tid] +
                        Rsum[tid] + Rsum[64 + tid] + Rsum[128 + tid] + Rsum[192 + tid];
            }
            const int cc = ph - 4;
            const int ai = 16 * wr + (lane & 15);
            const int cn = 16 * wc + (lane & 7) + ((lane >> 4) << 3);
            #pragma unroll
            for (int jc = 0; jc < 8; jc++) {
                uint32_t abyte = ai * 256 + ((jc * 32 + (lane >> 4) * 16) ^ ((ai & 7) << 4));
                uint32_t ph4[4], pl4[4];
                ldsm4(ph4, psh_b + abyte);
                ldsm4(pl4, psl_b + abyte);
                uint32_t bbyte = jc * 32 + ((lane >> 3) & 1) * 16;
                uint32_t va = bufb + cn * 256 + (bbyte ^ ((cn & 7) << 4));
                uint32_t vh4[4], vl4[4];
                ldsm4(vh4, va); ldsm4(vl4, va + 16384);
                mma16816(oa[cc][0], ph4, vh4);     mma16816(oa[cc][0], ph4, vl4);     mma16816(oa[cc][0], pl4, vh4);
                mma16816(oa[cc][1], ph4, vh4 + 2); mma16816(oa[cc][1], ph4, vl4 + 2); mma16816(oa[cc][1], pl4, vh4 + 2);
            }
        }
    }
    CP_WAIT(0);
    __syncthreads();

    const float inv0 = 1.f / l_s[r0], inv1 = 1.f / l_s[r1];
    #pragma unroll
    for (int cc = 0; cc < 4; cc++)
        #pragma unroll
        for (int nt = 0; nt < 2; nt++) {
            int c = 64 * cc + 16 * wc + 8 * nt + 2 * tr;
            size_t o0 = (size_t)(b * NC + c) * NPQ + i0;
            size_t o1 = (size_t)(b * NC + c + 1) * NPQ + i0;
            bf16 hh, ll;
            bfsplit(oa[cc][nt][0] * inv0, hh, ll); g_goh[o0 + r0] = hh; g_gol[o0 + r0] = ll;
            bfsplit(oa[cc][nt][1] * inv0, hh, ll); g_goh[o1 + r0] = hh; g_gol[o1 + r0] = ll;
            bfsplit(oa[cc][nt][2] * inv1, hh, ll); g_goh[o0 + r1] = hh; g_gol[o0 + r1] = ll;
            bfsplit(oa[cc][nt][3] * inv1, hh, ll); g_goh[o1 + r1] = hh; g_gol[o1 + r1] = ll;
        }
}

// ============================ output projection (mma.sync bf16) ============
// Same structure as qkv_kernel: A = Wo[o][c], B = go[c][p] (trans).
__global__ __launch_bounds__(512, 1) void proj_kernel(const float* __restrict__ bo)
{
    extern __shared__ char smq[];
    const uint32_t sb = (uint32_t)__cvta_generic_to_shared(smq);

    const int tid = threadIdx.x, lane = tid & 31, wid = tid >> 5;
    const int wr = wid & 3, wc = wid >> 2;
    const int tq = lane >> 2, tr = lane & 3;
    const int n0 = blockIdx.x * 64, m0 = blockIdx.y * 128, b = blockIdx.z;

    const int nfq = g_cnt[b * 2] + 1;
    if (n0 >= nfq) return;

    auto issue = [&](int ci, int buf) {
        char* st = smq + buf * 49152;
        const int kc = ci * 64;
        #pragma unroll
        for (int it = 0; it < 2; it++) {
            int idx = tid + it * 512;
            int m = idx >> 3, k16 = idx & 7;
            uint32_t d = m * 128 + ((k16 * 16) ^ ((m & 7) << 4));
            size_t s = (size_t)(m0 + m) * 256 + kc + k16 * 8;
            cp16(st + d, g_woh + s);
            cp16(st + 16384 + d, g_wol + s);
        }
        {
            int k = tid >> 3, n16 = tid & 7;
            uint32_t d = k * 128 + ((n16 * 16) ^ ((k & 7) << 4));
            size_t s = ((size_t)(b * NC) + kc + k) * NPQ + n0 + n16 * 8;
            cp16(st + 32768 + d, g_goh + s);
            cp16(st + 40960 + d, g_gol + s);
        }
        CP_COMMIT;
    };

    float acc[2][2][4];
    #pragma unroll
    for (int mt = 0; mt < 2; mt++)
        #pragma unroll
        for (int nt = 0; nt < 2; nt++)
            #pragma unroll
            for (int d = 0; d < 4; d++) acc[mt][nt][d] = 0.f;

    issue(0, 0);
    for (int ci = 0; ci < 4; ci++) {
        int nxt = (ci + 1 < 4) ? ci + 1 : 3;
        issue(nxt, (ci + 1) & 1);
        CP_WAIT(1);
        __syncthreads();
        const uint32_t wh_b = sb + (ci & 1) * 49152;
        const uint32_t wl_b = wh_b + 16384;
        const uint32_t xh_b = wh_b + 32768;
        const uint32_t xl_b = wh_b + 40960;

        #pragma unroll
        for (int kc = 0; kc < 4; kc++) {
            int krow = kc * 16 + (lane & 7) + ((lane >> 3) & 1) * 8;
            uint32_t nbyte = wc * 32 + ((lane >> 4) << 4);
            uint32_t xa = krow * 128 + (nbyte ^ ((krow & 7) << 4));
            uint32_t bh[4], bl[4];
            ldsm4t(bh, xh_b + xa);
            ldsm4t(bl, xl_b + xa);
            #pragma unroll
            for (int mt = 0; mt < 2; mt++) {
                int ai = wr * 32 + mt * 16 + (lane & 15);
                uint32_t abyte = ai * 128 + ((kc * 32 + (lane >> 4) * 16) ^ ((ai & 7) << 4));
                uint32_t ah[4], al[4];
                ldsm4(ah, wh_b + abyte);
                ldsm4(al, wl_b + abyte);
                mma16816(acc[mt][0], ah, bh);     mma16816(acc[mt][0], ah, bl);     mma16816(acc[mt][0], al, bh);
                mma16816(acc[mt][1], ah, bh + 2); mma16816(acc[mt][1], ah, bl + 2); mma16816(acc[mt][1], al, bh + 2);
            }
        }
        __syncthreads();
    }
    CP_WAIT(0);

    #pragma unroll
    for (int mt = 0; mt < 2; mt++)
        #pragma unroll
        for (int half = 0; half < 2; half++) {
            const int o = m0 + wr * 32 + mt * 16 + tq + half * 8;
            const float bb = bo[o];
            #pragma unroll
            for (int nt = 0; nt < 2; nt++)
                #pragma unroll
                for (int e = 0; e < 2; e++) {
                    int ng = n0 + wc * 16 + nt * 8 + tr * 2 + e;
                    g_p[(size_t)(b * NC + o) * NPQ + ng] = acc[mt][nt][half * 2 + e] + bb;
                }
        }
}

// ============================ scatter ======================================
__global__ __launch_bounds__(256, 1) void scatter_kernel(
    const float* __restrict__ x, const float* __restrict__ gamma,
    float* __restrict__ out)
{
    const int b = blockIdx.y;
    const int n = blockIdx.x * 256 + threadIdx.x;
    const int ci = g_cidx[(size_t)b * NP + n];
    const float g0 = gamma[0];
    const float* px = x + (size_t)b * NC * NP + n;
    const float* pp = g_p + (size_t)b * NC * NPQ + ci;
    float* po = out + (size_t)b * NC * NP + n;
    #pragma unroll 4
    for (int c = 0; c < NC; c++)
        po[(size_t)c * NP] = pp[(size_t)c * NPQ] + g0 * px[(size_t)c * NP];
}

extern "C" void kernel_launch(void* const* d_in, const int* in_sizes, int n_in,
                              void* d_out, int out_size)
{
    const float* x     = (const float*)d_in[0];
    const float* mask  = (const float*)d_in[1];
    const float* Wq    = (const float*)d_in[2];
    const float* bq    = (const float*)d_in[3];
    const float* Wk    = (const float*)d_in[4];
    const float* bk    = (const float*)d_in[5];
    const float* Wv    = (const float*)d_in[6];
    const float* bv    = (const float*)d_in[7];
    const float* Wo    = (const float*)d_in[8];
    const float* bo    = (const float*)d_in[9];
    const float* gamma = (const float*)d_in[10];
    float* out = (float*)d_out;

    compact_kernel<<<NB, 256>>>(mask);
    wsplit_kernel<<<1024, 256>>>(Wq, Wk, Wv, Wo);
    xsplit_kernel<<<(NB * NC * NP) / 1024, 256>>>(x);

    cudaFuncSetAttribute(qkv_kernel, cudaFuncAttributeMaxDynamicSharedMemorySize, 98304);
    qkv_kernel<<<dim3(64, 6, NB), 512, 98304>>>(mask, bq, bk, bv);

    pad_kernel<<<dim3(NB, 3), 256>>>(bq, bk, bv);

    const size_t smemB = 232192;
    cudaFuncSetAttribute(attn_kernel, cudaFuncAttributeMaxDynamicSharedMemorySize, (int)smemB);
    attn_kernel<<<dim3(65, NB), 512, smemB>>>();

    cudaFuncSetAttribute(proj_kernel, cudaFuncAttributeMaxDynamicSharedMemorySize, 98304);
    proj_kernel<<<dim3(65, 2, NB), 512, 98304>>>(bo);

    scatter_kernel<<<dim3(16, NB), 256>>>(x, gamma, out);
}

// round 15
// speedup vs baseline: 1.6275x; 1.0180x over previous
#include <cuda_runtime.h>
#include <cuda_bf16.h>
#include <cstdint>

#define NB 8
#define NC 256
#define NP 4096
#define NPQ 4224

typedef unsigned long long ull;
typedef __nv_bfloat16 bf16;

__device__ bf16  g_qh[NB * NPQ * NC];   // q hi [b][p][c]
__device__ bf16  g_ql[NB * NPQ * NC];
__device__ bf16  g_kh[NB * NPQ * NC];   // k hi [b][p][c]
__device__ bf16  g_kl[NB * NPQ * NC];
__device__ bf16  g_vh[NB * NC * NPQ];   // v hi [b][c][p]
__device__ bf16  g_vl[NB * NC * NPQ];
__device__ bf16  g_wh[768 * 256];       // stacked Wq/Wk/Wv hi [o][c]
__device__ bf16  g_wl[768 * 256];
__device__ bf16  g_woh[256 * 256];      // Wo hi [o][c]
__device__ bf16  g_wol[256 * 256];
__device__ bf16  g_xh[NB * NC * NP];    // x hi [b][c][n]
__device__ bf16  g_xl[NB * NC * NP];
__device__ bf16  g_goh[NB * NC * NPQ];  // attn out hi [b][c][p]
__device__ bf16  g_gol[NB * NC * NPQ];
__device__ float g_p [NB * NC * NPQ];
__device__ int   g_pr[NB * NP];
__device__ int   g_cidx[NB * NP];
__device__ int   g_cnt[NB * 2];

__device__ __forceinline__ void cp16(void* dst, const void* src) {
    unsigned s = (unsigned)__cvta_generic_to_shared(dst);
    asm volatile("cp.async.cg.shared.global [%0], [%1], 16;" :: "r"(s), "l"(src));
}
#define CP_COMMIT asm volatile("cp.async.commit_group;" ::: "memory")
#define CP_WAIT(n) asm volatile("cp.async.wait_group %0;" :: "n"(n) : "memory")

__device__ __forceinline__ void bfsplit(float x, bf16& h, bf16& l) {
    h = __float2bfloat16(x);
    l = __float2bfloat16(x - __bfloat162float(h));
}
__device__ __forceinline__ void split2(float a, float b, uint32_t& h, uint32_t& l) {
    bf16 ah, al, bh, bl;
    bfsplit(a, ah, al); bfsplit(b, bh, bl);
    h = (uint32_t)__bfloat16_as_ushort(ah) | ((uint32_t)__bfloat16_as_ushort(bh) << 16);
    l = (uint32_t)__bfloat16_as_ushort(al) | ((uint32_t)__bfloat16_as_ushort(bl) << 16);
}
__device__ __forceinline__ void ldsm4(uint32_t* r, uint32_t a) {
    asm volatile("ldmatrix.sync.aligned.m8n8.x4.shared.b16 {%0,%1,%2,%3}, [%4];"
        : "=r"(r[0]), "=r"(r[1]), "=r"(r[2]), "=r"(r[3]) : "r"(a));
}
__device__ __forceinline__ void ldsm4t(uint32_t* r, uint32_t a) {
    asm volatile("ldmatrix.sync.aligned.m8n8.x4.trans.shared.b16 {%0,%1,%2,%3}, [%4];"
        : "=r"(r[0]), "=r"(r[1]), "=r"(r[2]), "=r"(r[3]) : "r"(a));
}
__device__ __forceinline__ void mma16816(float* d, const uint32_t* a, const uint32_t* b) {
    asm volatile("mma.sync.aligned.m16n8k16.row.col.f32.bf16.bf16.f32 "
        "{%0,%1,%2,%3},{%4,%5,%6,%7},{%8,%9},{%0,%1,%2,%3};"
        : "+f"(d[0]), "+f"(d[1]), "+f"(d[2]), "+f"(d[3])
        : "r"(a[0]), "r"(a[1]), "r"(a[2]), "r"(a[3]), "r"(b[0]), "r"(b[1]));
}

// ============================ compaction ===================================
__global__ __launch_bounds__(256, 1) void compact_kernel(const float* __restrict__ mask)
{
    const int b = blockIdx.x, tid = threadIdx.x;
    const int lane = tid & 31, wid = tid >> 5;
    __shared__ int wsum[8];
    __shared__ int s_nf;
    bool f[16]; int c = 0;
    const float* mb = mask + (size_t)b * NP;
    #pragma unroll
    for (int i = 0; i < 16; i++) { f[i] = mb[tid * 16 + i] > 0.5f; c += f[i]; }
    int v = c;
    #pragma unroll
    for (int off = 1; off < 32; off <<= 1) {
        int u = __shfl_up_sync(0xffffffffu, v, off);
        if (lane >= off) v += u;
    }
    if (lane == 31) wsum[wid] = v;
    __syncthreads();
    if (tid < 8) {
        int wv = wsum[tid];
        #pragma unroll
        for (int off = 1; off < 8; off <<= 1) {
            int u = __shfl_up_sync(0xffu, wv, off);
            if (tid >= off) wv += u;
        }
        wsum[tid] = wv;
        if (tid == 7) s_nf = wv;
    }
    __syncthreads();
    const int nf = s_nf;
    int excl = v - c + (wid ? wsum[wid - 1] : 0);
    int fo = excl, bo = tid * 16 - excl;
    int* pr = g_pr + (size_t)b * NP;
    int* cidx = g_cidx + (size_t)b * NP;
    #pragma unroll
    for (int i = 0; i < 16; i++) {
        int n = tid * 16 + i;
        if (f[i]) { pr[n] = fo; cidx[n] = fo; fo++; }
        else      { pr[n] = bo; cidx[n] = nf; bo++; }
    }
    if (tid == 0) { g_cnt[b * 2] = nf; g_cnt[b * 2 + 1] = NP - nf; }
}

// ============================ W / x bf16 split prep ========================
__global__ __launch_bounds__(256, 4) void wsplit_kernel(
    const float* __restrict__ Wq, const float* __restrict__ Wk,
    const float* __restrict__ Wv, const float* __restrict__ Wo)
{
    const int row = blockIdx.x;        // 0..1023
    const int c = threadIdx.x;
    if (row < 768) {
        const float* W = (row < 256) ? Wq : ((row < 512) ? Wk : Wv);
        bf16 h, l; bfsplit(W[(row & 255) * 256 + c], h, l);
        g_wh[row * 256 + c] = h;
        g_wl[row * 256 + c] = l;
    } else {
        bf16 h, l; bfsplit(Wo[(row & 255) * 256 + c], h, l);
        g_woh[(row & 255) * 256 + c] = h;
        g_wol[(row & 255) * 256 + c] = l;
    }
}

__global__ __launch_bounds__(256, 4) void xsplit_kernel(const float* __restrict__ x)
{
    const size_t i = ((size_t)blockIdx.x * 256 + threadIdx.x) * 4;
    float4 v = *reinterpret_cast<const float4*>(x + i);
    uint32_t h0, l0, h1, l1;
    split2(v.x, v.y, h0, l0);
    split2(v.z, v.w, h1, l1);
    *reinterpret_cast<uint2*>(g_xh + i) = make_uint2(h0, h1);
    *reinterpret_cast<uint2*>(g_xl + i) = make_uint2(l0, l1);
}

// ============================ QKV projection (mma.sync bf16, N=128) ========
// 512 thr = 16 warps: wr=wid&3 -> 32 m-rows, wc=wid>>2 -> 32 n-cols.
// Tile M=128 x N=128, K=256 in four 64-k chunks, 2-stage cp.async.
// Stage layout (64KB): wh 0..16K, wl 16..32K, xh 32..48K (64k x 128n, 256B
// rows), xl 48..64K. Swizzle: byte16-unit ^= (row&7).
__global__ __launch_bounds__(512, 1) void qkv_kernel(
    const float* __restrict__ mask, const float* __restrict__ bq,
    const float* __restrict__ bk, const float* __restrict__ bv)
{
    extern __shared__ char smq[];
    const uint32_t sb = (uint32_t)__cvta_generic_to_shared(smq);

    const int tid = threadIdx.x, lane = tid & 31, wid = tid >> 5;
    const int wr = wid & 3, wc = wid >> 2;
    const int tq = lane >> 2, tr = lane & 3;
    const int n0 = blockIdx.x * 128, m0 = blockIdx.y * 128, b = blockIdx.z;

    auto issue = [&](int ci, int buf) {
        char* st = smq + buf * 65536;
        const int kc = ci * 64;
        // W: 128 rows x 8 units (128B rows) = 1024 transfers
        #pragma unroll
        for (int it = 0; it < 2; it++) {
            int idx = tid + it * 512;
            int m = idx >> 3, k16 = idx & 7;
            uint32_t d = m * 128 + ((k16 * 16) ^ ((m & 7) << 4));
            size_t s = (size_t)(m0 + m) * 256 + kc + k16 * 8;
            cp16(st + d, g_wh + s);
            cp16(st + 16384 + d, g_wl + s);
        }
        // x: 64 rows x 16 units (256B rows) = 1024 transfers
        #pragma unroll
        for (int it = 0; it < 2; it++) {
            int idx = tid + it * 512;
            int k = idx >> 4, n16 = idx & 15;
            uint32_t d = k * 256 + ((n16 * 16) ^ ((k & 7) << 4));
            size_t s = ((size_t)(b * NC) + kc + k) * NP + n0 + n16 * 8;
            cp16(st + 32768 + d, g_xh + s);
            cp16(st + 49152 + d, g_xl + s);
        }
        CP_COMMIT;
    };

    float acc[2][4][4];
    #pragma unroll
    for (int mt = 0; mt < 2; mt++)
        #pragma unroll
        for (int nt = 0; nt < 4; nt++)
            #pragma unroll
            for (int d = 0; d < 4; d++) acc[mt][nt][d] = 0.f;

    issue(0, 0);
    for (int ci = 0; ci < 4; ci++) {
        int nxt = (ci + 1 < 4) ? ci + 1 : 3;
        issue(nxt, (ci + 1) & 1);
        CP_WAIT(1);
        __syncthreads();
        const uint32_t wh_b = sb + (ci & 1) * 65536;
        const uint32_t wl_b = wh_b + 16384;
        const uint32_t xh_b = wh_b + 32768;
        const uint32_t xl_b = wh_b + 49152;

        #pragma unroll
        for (int kc = 0; kc < 4; kc++) {
            int krow = kc * 16 + (lane & 7) + ((lane >> 3) & 1) * 8;
            uint32_t bh[2][4], bl[2][4];
            #pragma unroll
            for (int s = 0; s < 2; s++) {
                uint32_t nbyte = wc * 64 + s * 32 + ((lane >> 4) << 4);
                uint32_t xa = krow * 256 + (nbyte ^ ((krow & 7) << 4));
                ldsm4t(bh[s], xh_b + xa);
                ldsm4t(bl[s], xl_b + xa);
            }
            #pragma unroll
            for (int mt = 0; mt < 2; mt++) {
                int ai = wr * 32 + mt * 16 + (lane & 15);
                uint32_t abyte = ai * 128 + ((kc * 32 + (lane >> 4) * 16) ^ ((ai & 7) << 4));
                uint32_t ah[4], al[4];
                ldsm4(ah, wh_b + abyte);
                ldsm4(al, wl_b + abyte);
                #pragma unroll
                for (int s = 0; s < 2; s++) {
                    mma16816(acc[mt][s*2+0], ah, bh[s]);     mma16816(acc[mt][s*2+0], ah, bl[s]);     mma16816(acc[mt][s*2+0], al, bh[s]);
                    mma16816(acc[mt][s*2+1], ah, bh[s] + 2); mma16816(acc[mt][s*2+1], ah, bl[s] + 2); mma16816(acc[mt][s*2+1], al, bh[s] + 2);
                }
            }
        }
        __syncthreads();
    }
    CP_WAIT(0);

    const int sel = m0 >> 8;
    float mk[4][2]; int pr_[4][2];
    #pragma unroll
    for (int nt = 0; nt < 4; nt++)
        #pragma unroll
        for (int e = 0; e < 2; e++) {
            int ng = n0 + wc * 32 + nt * 8 + tr * 2 + e;
            mk[nt][e] = mask[(size_t)b * NP + ng];
            pr_[nt][e] = g_pr[(size_t)b * NP + ng];
        }

    #pragma unroll
    for (int mt = 0; mt < 2; mt++)
        #pragma unroll
        for (int half = 0; half < 2; half++) {
            const int o = (m0 & 255) + wr * 32 + mt * 16 + tq + half * 8;
            if (sel == 0) {
                const float bb = bq[o];
                #pragma unroll
                for (int nt = 0; nt < 4; nt++)
                    #pragma unroll
                    for (int e = 0; e < 2; e++)
                        if (mk[nt][e] > 0.5f) {
                            bf16 hh, ll; bfsplit(acc[mt][nt][half * 2 + e] + bb, hh, ll);
                            size_t off = ((size_t)b * NPQ + pr_[nt][e]) * NC + o;
                            g_qh[off] = hh; g_ql[off] = ll;
                        }
            } else if (sel == 1) {
                const float bb = bk[o];
                #pragma unroll
                for (int nt = 0; nt < 4; nt++)
                    #pragma unroll
                    for (int e = 0; e < 2; e++)
                        if (mk[nt][e] < 0.5f) {
                            bf16 hh, ll; bfsplit(acc[mt][nt][half * 2 + e] + bb, hh, ll);
                            size_t off = ((size_t)b * NPQ + pr_[nt][e]) * NC + o;
                            g_kh[off] = hh; g_kl[off] = ll;
                        }
            } else {
                const float bb = bv[o];
                #pragma unroll
                for (int nt = 0; nt < 4; nt++)
                    #pragma unroll
                    for (int e = 0; e < 2; e++)
                        if (mk[nt][e] < 0.5f) {
                            bf16 hh, ll; bfsplit(acc[mt][nt][half * 2 + e] + bb, hh, ll);
                            size_t off = ((size_t)b * NC + o) * NPQ + pr_[nt][e];
                            g_vh[off] = hh; g_vl[off] = ll;
                        }
            }
        }
}

// ============================ pad ==========================================
__global__ __launch_bounds__(256, 1) void pad_kernel(
    const float* __restrict__ bq, const float* __restrict__ bk,
    const float* __restrict__ bv)
{
    const int b = blockIdx.x, sec = blockIdx.y, tid = threadIdx.x;
    const int nf = g_cnt[b * 2], nb = g_cnt[b * 2 + 1];
    if (sec == 0) {
        const int NQ = ((nf + 64) >> 6) << 6;
        const int tot = (NQ - nf) * NC;
        for (int idx = tid; idx < tot; idx += 256) {
            int p = nf + (idx >> 8), c = idx & 255;
            bf16 h(__float2bfloat16(0.f)), l(__float2bfloat16(0.f));
            if (p == nf) bfsplit(bq[c], h, l);
            size_t off = ((size_t)b * NPQ + p) * NC + c;
            g_qh[off] = h; g_ql[off] = l;
        }
    } else if (sec == 1) {
        const int NK = ((nb + 128) >> 7) << 7;
        const int tot = (NK - nb) * NC;
        for (int idx = tid; idx < tot; idx += 256) {
            int p = nb + (idx >> 8), c = idx & 255;
            bf16 h(__float2bfloat16(0.f)), l(__float2bfloat16(0.f));
            if (p == nb) bfsplit(bk[c], h, l);
            size_t off = ((size_t)b * NPQ + p) * NC + c;
            g_kh[off] = h; g_kl[off] = l;
        }
    } else {
        const int NK = ((nb + 128) >> 7) << 7;
        for (int p = nb; p < NK; p++) {
            bf16 h(__float2bfloat16(0.f)), l(__float2bfloat16(0.f));
            if (p == nb) bfsplit(bv[tid], h, l);
            size_t off = ((size_t)b * NC + tid) * NPQ + p;
            g_vh[off] = h; g_vl[off] = l;
        }
    }
}

// ============================ flash attention (mma.sync bf16) ==============
__global__ __launch_bounds__(512, 1) void attn_kernel()
{
    extern __shared__ char smc[];
    char* Pool = smc + 65536;
    char* Psh  = smc + 196608;
    char* Psl  = smc + 212992;
    float* Red = (float*)(smc + 229376);
    float* m_s = Red; float* l_s = Red + 64; float* A_s = Red + 128;
    float* Rmax = Red + 192; float* Rsum = Red + 448;

    const uint32_t sb = (uint32_t)__cvta_generic_to_shared(smc);
    const uint32_t qh_b = sb, ql_b = sb + 32768;
    const uint32_t pool_b = sb + 65536;
    const uint32_t psh_b = sb + 196608, psl_b = sb + 212992;

    const int tid = threadIdx.x, lane = tid & 31, wid = tid >> 5;
    const int wr = wid & 3, wc = wid >> 2;
    const int tq = lane >> 2, tr = lane & 3;
    const int b = blockIdx.y, i0 = blockIdx.x * 64;

    const int nf = g_cnt[b * 2], nb = g_cnt[b * 2 + 1];
    if (i0 >= nf + 1) return;
    const int nkt = (nb + 128) >> 7;
    const float wF = (float)nf;
    const int r0 = 16 * wr + tq, r1 = r0 + 8;

    auto loadK = [&](int ck, int j0, char* buf) {
        #pragma unroll
        for (int it = 0; it < 2; it++) {
            int idx = tid + it * 512;
            int j = idx >> 3, c16 = idx & 7;
            uint32_t d = j * 128 + ((c16 * 16) ^ ((j & 7) << 4));
            size_t s = ((size_t)b * NPQ + j0 + j) * NC + ck * 64 + c16 * 8;
            cp16(buf + d, g_kh + s);
            cp16(buf + 16384 + d, g_kl + s);
        }
        CP_COMMIT;
    };
    auto loadV = [&](int cc, int j0, char* buf) {
        #pragma unroll
        for (int it = 0; it < 2; it++) {
            int idx = tid + it * 512;
            int c = idx >> 4, j16 = idx & 15;
            uint32_t d = c * 256 + ((j16 * 16) ^ ((c & 7) << 4));
            size_t s = ((size_t)b * NC + cc * 64 + c) * NPQ + j0 + j16 * 8;
            cp16(buf + d, g_vh + s);
            cp16(buf + 16384 + d, g_vl + s);
        }
        CP_COMMIT;
    };

    #pragma unroll
    for (int it = 0; it < 4; it++) {
        int idx = tid + it * 512;
        int i = idx >> 5, c16 = idx & 31;
        uint32_t d = i * 512 + ((c16 * 16) ^ ((i & 7) << 4));
        size_t s = ((size_t)b * NPQ + i0 + i) * NC + c16 * 8;
        cp16(smc + d, g_qh + s);
        cp16(smc + 32768 + d, g_ql + s);
    }
    loadK(0, 0, Pool);
    loadK(1, 0, Pool + 32768);

    if (tid < 64) { m_s[tid] = -1e30f; l_s[tid] = 0.f; }

    float sacc[4][4];
    float oa[4][2][4];
    #pragma unroll
    for (int cc = 0; cc < 4; cc++)
        #pragma unroll
        for (int nt = 0; nt < 2; nt++)
            #pragma unroll
            for (int d = 0; d < 4; d++) oa[cc][nt][d] = 0.f;

    const int qtot = nkt * 8;
    for (int q = 0; q < qtot; q++) {
        CP_WAIT(1);
        __syncthreads();
        const int q2 = q + 2;
        if (q2 < qtot) {
            char* buf2 = Pool + (q2 & 3) * 32768;
            int jt2 = q2 >> 3, ph2 = q2 & 7;
            if (ph2 < 4) loadK(ph2, jt2 << 7, buf2);
            else loadV(ph2 - 4, jt2 << 7, buf2);
        } else CP_COMMIT;

        const int ph = q & 7, jt = q >> 3;
        const uint32_t bufb = pool_b + (q & 3) * 32768;

        if (ph < 4) {
            if (ph == 0) {
                #pragma unroll
                for (int nt = 0; nt < 4; nt++)
                    #pragma unroll
                    for (int d = 0; d < 4; d++) sacc[nt][d] = 0.f;
            }
            const int ai = 16 * wr + (lane & 15);
            const int bj = 32 * wc + (lane & 7) + ((lane >> 4) << 3);
            const int bj1 = bj + 16;
            #pragma unroll
            for (int kc = 0; kc < 4; kc++) {
                uint32_t abyte = ai * 512 +
                    ((((ph * 64 + kc * 16) * 2) + (lane >> 4) * 16) ^ ((ai & 7) << 4));
                uint32_t ah[4], al[4];
                ldsm4(ah, qh_b + abyte);
                ldsm4(al, ql_b + abyte);
                uint32_t bbyte = kc * 32 + ((lane >> 3) & 1) * 16;
                uint32_t ka0 = bufb + bj * 128 + (bbyte ^ ((bj & 7) << 4));
                uint32_t ka1 = bufb + bj1 * 128 + (bbyte ^ ((bj1 & 7) << 4));
                uint32_t bh0[4], bl0[4], bh1[4], bl1[4];
                ldsm4(bh0, ka0); ldsm4(bl0, ka0 + 16384);
                ldsm4(bh1, ka1); ldsm4(bl1, ka1 + 16384);
                mma16816(sacc[0], ah, bh0);     mma16816(sacc[0], ah, bl0);     mma16816(sacc[0], al, bh0);
                mma16816(sacc[1], ah, bh0 + 2); mma16816(sacc[1], ah, bl0 + 2); mma16816(sacc[1], al, bh0 + 2);
                mma16816(sacc[2], ah, bh1);     mma16816(sacc[2], ah, bl1);     mma16816(sacc[2], al, bh1);
                mma16816(sacc[3], ah, bh1 + 2); mma16816(sacc[3], ah, bl1 + 2); mma16816(sacc[3], al, bh1 + 2);
            }
        } else {
            if (ph == 4) {
                const int j0 = jt << 7;
                float mx0 = -1e30f, mx1 = -1e30f;
                #pragma unroll
                for (int nt = 0; nt < 4; nt++)
                    #pragma unroll
                    for (int e = 0; e < 2; e++) {
                        int jg = j0 + 32 * wc + 8 * nt + 2 * tr + e;
                        if (jg > nb) { sacc[nt][e] = -1e30f; sacc[nt][2 + e] = -1e30f; }
                        mx0 = fmaxf(mx0, sacc[nt][e]);
                        mx1 = fmaxf(mx1, sacc[nt][2 + e]);
                    }
                #pragma unroll
                for (int off = 1; off < 4; off <<= 1) {
                    mx0 = fmaxf(mx0, __shfl_xor_sync(0xffffffffu, mx0, off));
                    mx1 = fmaxf(mx1, __shfl_xor_sync(0xffffffffu, mx1, off));
                }
                if (tr == 0) { Rmax[wc * 64 + r0] = mx0; Rmax[wc * 64 + r1] = mx1; }
                __syncthreads();
                if (tid < 64) {
                    float mt = fmaxf(fmaxf(Rmax[tid], Rmax[64 + tid]),
                                     fmaxf(Rmax[128 + tid], Rmax[192 + tid]));
                    float mo = m_s[tid];
                    float mn = fmaxf(mo, mt);
                    m_s[tid] = mn;
                    A_s[tid] = __expf(mo - mn);
                }
                __syncthreads();
                const float mn0 = m_s[r0], mn1 = m_s[r1];
                const float a0 = A_s[r0], a1 = A_s[r1];
                #pragma unroll
                for (int cc = 0; cc < 4; cc++)
                    #pragma unroll
                    for (int nt = 0; nt < 2; nt++) {
                        oa[cc][nt][0] *= a0; oa[cc][nt][1] *= a0;
                        oa[cc][nt][2] *= a1; oa[cc][nt][3] *= a1;
                    }
                float sm0 = 0.f, sm1 = 0.f;
                #pragma unroll
                for (int nt = 0; nt < 4; nt++) {
                    int jg0 = j0 + 32 * wc + 8 * nt + 2 * tr;
                    float w0 = (jg0 == nb) ? wF : 1.f;
                    float w1 = (jg0 + 1 == nb) ? wF : 1.f;
                    float p00 = __expf(sacc[nt][0] - mn0) * w0;
                    float p01 = __expf(sacc[nt][1] - mn0) * w1;
                    float p10 = __expf(sacc[nt][2] - mn1) * w0;
                    float p11 = __expf(sacc[nt][3] - mn1) * w1;
                    sm0 += p00 + p01; sm1 += p10 + p11;
                    uint32_t h, l;
                    int colb = (32 * wc + 8 * nt + 2 * tr) * 2;
                    split2(p00, p01, h, l);
                    *(uint32_t*)(Psh + r0 * 256 + (colb ^ ((r0 & 7) << 4))) = h;
                    *(uint32_t*)(Psl + r0 * 256 + (colb ^ ((r0 & 7) << 4))) = l;
                    split2(p10, p11, h, l);
                    *(uint32_t*)(Psh + r1 * 256 + (colb ^ ((r1 & 7) << 4))) = h;
                    *(uint32_t*)(Psl + r1 * 256 + (colb ^ ((r1 & 7) << 4))) = l;
                }
                #pragma unroll
                for (int off = 1; off < 4; off <<= 1) {
                    sm0 += __shfl_xor_sync(0xffffffffu, sm0, off);
                    sm1 += __shfl_xor_sync(0xffffffffu, sm1, off);
                }
                if (tr == 0) { Rsum[wc * 64 + r0] = sm0; Rsum[wc * 64 + r1] = sm1; }
                __syncthreads();
                if (tid < 64)
                    l_s[tid] = l_s[tid] * A_s[tid] +
                        Rsum[tid] + Rsum[64 + tid] + Rsum[128 + tid] + Rsum[192 + tid];
            }
            const int cc = ph - 4;
            const int ai = 16 * wr + (lane & 15);
            const int cn = 16 * wc + (lane & 7) + ((lane >> 4) << 3);
            #pragma unroll
            for (int jc = 0; jc < 8; jc++) {
                uint32_t abyte = ai * 256 + ((jc * 32 + (lane >> 4) * 16) ^ ((ai & 7) << 4));
                uint32_t ph4[4], pl4[4];
                ldsm4(ph4, psh_b + abyte);
                ldsm4(pl4, psl_b + abyte);
                uint32_t bbyte = jc * 32 + ((lane >> 3) & 1) * 16;
                uint32_t va = bufb + cn * 256 + (bbyte ^ ((cn & 7) << 4));
                uint32_t vh4[4], vl4[4];
                ldsm4(vh4, va); ldsm4(vl4, va + 16384);
                mma16816(oa[cc][0], ph4, vh4);     mma16816(oa[cc][0], ph4, vl4);     mma16816(oa[cc][0], pl4, vh4);
                mma16816(oa[cc][1], ph4, vh4 + 2); mma16816(oa[cc][1], ph4, vl4 + 2); mma16816(oa[cc][1], pl4, vh4 + 2);
            }
        }
    }
    CP_WAIT(0);
    __syncthreads();

    const float inv0 = 1.f / l_s[r0], inv1 = 1.f / l_s[r1];
    #pragma unroll
    for (int cc = 0; cc < 4; cc++)
        #pragma unroll
        for (int nt = 0; nt < 2; nt++) {
            int c = 64 * cc + 16 * wc + 8 * nt + 2 * tr;
            size_t o0 = (size_t)(b * NC + c) * NPQ + i0;
            size_t o1 = (size_t)(b * NC + c + 1) * NPQ + i0;
            bf16 hh, ll;
            bfsplit(oa[cc][nt][0] * inv0, hh, ll); g_goh[o0 + r0] = hh; g_gol[o0 + r0] = ll;
            bfsplit(oa[cc][nt][1] * inv0, hh, ll); g_goh[o1 + r0] = hh; g_gol[o1 + r0] = ll;
            bfsplit(oa[cc][nt][2] * inv1, hh, ll); g_goh[o0 + r1] = hh; g_gol[o0 + r1] = ll;
            bfsplit(oa[cc][nt][3] * inv1, hh, ll); g_goh[o1 + r1] = hh; g_gol[o1 + r1] = ll;
        }
}

// ============================ output projection (mma.sync bf16) ============
__global__ __launch_bounds__(512, 1) void proj_kernel(const float* __restrict__ bo)
{
    extern __shared__ char smq[];
    const uint32_t sb = (uint32_t)__cvta_generic_to_shared(smq);

    const int tid = threadIdx.x, lane = tid & 31, wid = tid >> 5;
    const int wr = wid & 3, wc = wid >> 2;
    const int tq = lane >> 2, tr = lane & 3;
    const int n0 = blockIdx.x * 64, m0 = blockIdx.y * 128, b = blockIdx.z;

    const int nfq = g_cnt[b * 2] + 1;
    if (n0 >= nfq) return;

    auto issue = [&](int ci, int buf) {
        char* st = smq + buf * 49152;
        const int kc = ci * 64;
        #pragma unroll
        for (int it = 0; it < 2; it++) {
            int idx = tid + it * 512;
            int m = idx >> 3, k16 = idx & 7;
            uint32_t d = m * 128 + ((k16 * 16) ^ ((m & 7) << 4));
            size_t s = (size_t)(m0 + m) * 256 + kc + k16 * 8;
            cp16(st + d, g_woh + s);
            cp16(st + 16384 + d, g_wol + s);
        }
        {
            int k = tid >> 3, n16 = tid & 7;
            uint32_t d = k * 128 + ((n16 * 16) ^ ((k & 7) << 4));
            size_t s = ((size_t)(b * NC) + kc + k) * NPQ + n0 + n16 * 8;
            cp16(st + 32768 + d, g_goh + s);
            cp16(st + 40960 + d, g_gol + s);
        }
        CP_COMMIT;
    };

    float acc[2][2][4];
    #pragma unroll
    for (int mt = 0; mt < 2; mt++)
        #pragma unroll
        for (int nt = 0; nt < 2; nt++)
            #pragma unroll
            for (int d = 0; d < 4; d++) acc[mt][nt][d] = 0.f;

    issue(0, 0);
    for (int ci = 0; ci < 4; ci++) {
        int nxt = (ci + 1 < 4) ? ci + 1 : 3;
        issue(nxt, (ci + 1) & 1);
        CP_WAIT(1);
        __syncthreads();
        const uint32_t wh_b = sb + (ci & 1) * 49152;
        const uint32_t wl_b = wh_b + 16384;
        const uint32_t xh_b = wh_b + 32768;
        const uint32_t xl_b = wh_b + 40960;

        #pragma unroll
        for (int kc = 0; kc < 4; kc++) {
            int krow = kc * 16 + (lane & 7) + ((lane >> 3) & 1) * 8;
            uint32_t nbyte = wc * 32 + ((lane >> 4) << 4);
            uint32_t xa = krow * 128 + (nbyte ^ ((krow & 7) << 4));
            uint32_t bh[4], bl[4];
            ldsm4t(bh, xh_b + xa);
            ldsm4t(bl, xl_b + xa);
            #pragma unroll
            for (int mt = 0; mt < 2; mt++) {
                int ai = wr * 32 + mt * 16 + (lane & 15);
                uint32_t abyte = ai * 128 + ((kc * 32 + (lane >> 4) * 16) ^ ((ai & 7) << 4));
                uint32_t ah[4], al[4];
                ldsm4(ah, wh_b + abyte);
                ldsm4(al, wl_b + abyte);
                mma16816(acc[mt][0], ah, bh);     mma16816(acc[mt][0], ah, bl);     mma16816(acc[mt][0], al, bh);
                mma16816(acc[mt][1], ah, bh + 2); mma16816(acc[mt][1], ah, bl + 2); mma16816(acc[mt][1], al, bh + 2);
            }
        }
        __syncthreads();
    }
    CP_WAIT(0);

    #pragma unroll
    for (int mt = 0; mt < 2; mt++)
        #pragma unroll
        for (int half = 0; half < 2; half++) {
            const int o = m0 + wr * 32 + mt * 16 + tq + half * 8;
            const float bb = bo[o];
            #pragma unroll
            for (int nt = 0; nt < 2; nt++)
                #pragma unroll
                for (int e = 0; e < 2; e++) {
                    int ng = n0 + wc * 16 + nt * 8 + tr * 2 + e;
                    g_p[(size_t)(b * NC + o) * NPQ + ng] = acc[mt][nt][half * 2 + e] + bb;
                }
        }
}

// ============================ scatter ======================================
__global__ __launch_bounds__(256, 1) void scatter_kernel(
    const float* __restrict__ x, const float* __restrict__ gamma,
    float* __restrict__ out)
{
    const int b = blockIdx.y;
    const int n = blockIdx.x * 256 + threadIdx.x;
    const int ci = g_cidx[(size_t)b * NP + n];
    const float g0 = gamma[0];
    const float* px = x + (size_t)b * NC * NP + n;
    const float* pp = g_p + (size_t)b * NC * NPQ + ci;
    float* po = out + (size_t)b * NC * NP + n;
    #pragma unroll 4
    for (int c = 0; c < NC; c++)
        po[(size_t)c * NP] = pp[(size_t)c * NPQ] + g0 * px[(size_t)c * NP];
}

extern "C" void kernel_launch(void* const* d_in, const int* in_sizes, int n_in,
                              void* d_out, int out_size)
{
    const float* x     = (const float*)d_in[0];
    const float* mask  = (const float*)d_in[1];
    const float* Wq    = (const float*)d_in[2];
    const float* bq    = (const float*)d_in[3];
    const float* Wk    = (const float*)d_in[4];
    const float* bk    = (const float*)d_in[5];
    const float* Wv    = (const float*)d_in[6];
    const float* bv    = (const float*)d_in[7];
    const float* Wo    = (const float*)d_in[8];
    const float* bo    = (const float*)d_in[9];
    const float* gamma = (const float*)d_in[10];
    float* out = (float*)d_out;

    compact_kernel<<<NB, 256>>>(mask);
    wsplit_kernel<<<1024, 256>>>(Wq, Wk, Wv, Wo);
    xsplit_kernel<<<(NB * NC * NP) / 1024, 256>>>(x);

    cudaFuncSetAttribute(qkv_kernel, cudaFuncAttributeMaxDynamicSharedMemorySize, 131072);
    qkv_kernel<<<dim3(32, 6, NB), 512, 131072>>>(mask, bq, bk, bv);

    pad_kernel<<<dim3(NB, 3), 256>>>(bq, bk, bv);

    const size_t smemB = 232192;
    cudaFuncSetAttribute(attn_kernel, cudaFuncAttributeMaxDynamicSharedMemorySize, (int)smemB);
    attn_kernel<<<dim3(65, NB), 512, smemB>>>();

    cudaFuncSetAttribute(proj_kernel, cudaFuncAttributeMaxDynamicSharedMemorySize, 98304);
    proj_kernel<<<dim3(65, 2, NB), 512, 98304>>>(bo);

    scatter_kernel<<<dim3(16, NB), 256>>>(x, gamma, out);
}